// round 3
// baseline (speedup 1.0000x reference)
#include <cuda_runtime.h>
#include <cuda_bf16.h>
#include <math.h>

// Problem constants
#define SQ   1024
#define DM   1024
#define NH   16
#define DKH  64
#define BSZ  2
#define MROWS (BSZ*SQ)

typedef unsigned long long u64;

// Packed f32x2 helpers (FFMA2 path -- only reachable via PTX)
#define FMA2(d,a,b,c) asm("fma.rn.f32x2 %0, %1, %2, %3;" : "=l"(d) : "l"(a), "l"(b), "l"(c))
#define MUL2(d,a,b)   asm("mul.rn.f32x2 %0, %1, %2;"     : "=l"(d) : "l"(a), "l"(b))
#define PACK2(d,lo,hi)   asm("mov.b64 %0, {%1,%2};" : "=l"(d) : "f"(lo), "f"(hi))
#define UNPACK2(lo,hi,s) asm("mov.b64 {%0,%1}, %2;" : "=f"(lo), "=f"(hi) : "l"(s))
#define NEG2(d,s) asm("xor.b64 %0, %1, 0x8000000080000000;" : "=l"(d) : "l"(s))

// Scratch (static device globals -- allocation-free per harness rules)
__device__ float g_W[4][DM*DM];        // big quaternion weight matrices q,k,v,o
__device__ float g_P[3][MROWS*DM];     // projected Q,K,V
__device__ float g_O[MROWS*DM];        // attention output

__constant__ int   c_SRC[16] = {0,1,2,3,  1,0,3,2,  2,3,0,1,  3,2,1,0};
__constant__ float c_SGN[16] = {1.f,1.f,1.f,1.f,  -1.f,1.f,-1.f,1.f,
                                -1.f,1.f,1.f,-1.f, -1.f,-1.f,1.f,1.f};

struct WPtrs { const float* w[16]; };
struct GemmArgs { const float* A[3]; const float* bias[3]; };

// ---------------------------------------------------------------------------
__global__ void build_wbig_kernel(WPtrs p) {
    int idx   = blockIdx.x * 256 + threadIdx.x;
    int which = idx >> 20;
    int e     = idx & ((1 << 20) - 1);
    int k     = e >> 10;
    int n     = e & 1023;
    int rb = k >> 8, kk = k & 255;
    int cb = n >> 8, nn = n & 255;
    float v = c_SGN[rb*4+cb] * p.w[which*4 + c_SRC[rb*4+cb]][kk*256 + nn];
    g_W[which][k*DM + n] = v;
}

// ---------------------------------------------------------------------------
// Shared GEMM body: C[128,128 tile] = A @ W + bias, FFMA2 inner loop.
// ---------------------------------------------------------------------------
__device__ __forceinline__
void gemm_body(const float* __restrict__ A, const float* __restrict__ W,
               const float* __restrict__ bias, float* __restrict__ C)
{
    __shared__ float As[16][128];
    __shared__ float Bs[16][128];

    int tid = threadIdx.x;
    int m0 = blockIdx.y * 128, n0 = blockIdx.x * 128;
    int tm = (tid >> 4) * 8, tn = (tid & 15) * 8;

    u64 accp[8][4];
#pragma unroll
    for (int i = 0; i < 8; i++)
#pragma unroll
        for (int j = 0; j < 4; j++) accp[i][j] = 0ull;

    for (int k0 = 0; k0 < DM; k0 += 16) {
#pragma unroll
        for (int i = 0; i < 2; i++) {
            int idx = tid + i * 256;
            int ar = idx >> 2, akc = (idx & 3) * 4;
            float4 a = *(const float4*)(A + (size_t)(m0 + ar) * DM + k0 + akc);
            As[akc + 0][ar] = a.x; As[akc + 1][ar] = a.y;
            As[akc + 2][ar] = a.z; As[akc + 3][ar] = a.w;
            int br = idx >> 5, bc = (idx & 31) * 4;
            *(float4*)&Bs[br][bc] =
                *(const float4*)(W + (size_t)(k0 + br) * DM + n0 + bc);
        }
        __syncthreads();
#pragma unroll
        for (int k = 0; k < 16; k++) {
            float a[8];
            *(float4*)(a)     = *(float4*)&As[k][tm];
            *(float4*)(a + 4) = *(float4*)&As[k][tm + 4];
            ulonglong2 b01 = *(const ulonglong2*)&Bs[k][tn];
            ulonglong2 b23 = *(const ulonglong2*)&Bs[k][tn + 4];
            u64 bp[4] = {b01.x, b01.y, b23.x, b23.y};
            u64 ap[8];
#pragma unroll
            for (int i = 0; i < 8; i++) PACK2(ap[i], a[i], a[i]);
#pragma unroll
            for (int i = 0; i < 8; i++)
#pragma unroll
                for (int j = 0; j < 4; j++)
                    FMA2(accp[i][j], ap[i], bp[j], accp[i][j]);
        }
        __syncthreads();
    }

#pragma unroll
    for (int i = 0; i < 8; i++) {
        float out[8];
#pragma unroll
        for (int j = 0; j < 4; j++) UNPACK2(out[2*j], out[2*j+1], accp[i][j]);
#pragma unroll
        for (int j = 0; j < 8; j++) out[j] += bias[n0 + tn + j];
        float* crow = C + (size_t)(m0 + tm + i) * DM + n0 + tn;
        *(float4*)(crow)     = *(float4*)(out);
        *(float4*)(crow + 4) = *(float4*)(out + 4);
    }
}

// Fused Q/K/V projection: blockIdx.z selects which GEMM.
__global__ __launch_bounds__(256)
void qkv_gemm_kernel(GemmArgs args)
{
    int z = blockIdx.z;
    gemm_body(args.A[z], g_W[z], args.bias[z], g_P[z]);
}

// Output projection: g_O @ W[3] + bo -> d_out
__global__ __launch_bounds__(256)
void o_gemm_kernel(const float* __restrict__ bias, float* __restrict__ Cout)
{
    gemm_body(g_O, g_W[3], bias, Cout);
}

// ---------------------------------------------------------------------------
// Quaternion flash attention, FFMA2 version.
// Grid: (S/32, B*H). Block 256 = (tx 0..15, ty 0..15).
// Thread handles query rows m = ty*2+{0,1}; key columns n = in*16+tx (in 0..3);
// output dims d = tx*4..tx*4+3.
// ---------------------------------------------------------------------------
#define KS_STRIDE 66
#define ATT_SMEM_FLOATS (2048 + 64*KS_STRIDE + 4096 + 8192)

__global__ __launch_bounds__(256)
void quat_attn_kernel(const int* __restrict__ mask)
{
    extern __shared__ float smemf[];
    float* Qs = smemf;                         // [32][64]
    float* Ks = smemf + 2048;                  // [64][66]
    float* Vs = smemf + 2048 + 64*KS_STRIDE;   // [64][64]
    float* Ps = Vs + 4096;                     // [4][32][64]

    int tid = threadIdx.x;
    int tx = tid & 15, ty = tid >> 4;
    int bh = blockIdx.y;
    int b = bh >> 4, h = bh & 15;
    int q0 = blockIdx.x * 32;

    const float* Qg = g_P[0] + (size_t)(b * SQ) * DM + h * DKH;
    const float* Kg = g_P[1] + (size_t)(b * SQ) * DM + h * DKH;
    const float* Vg = g_P[2] + (size_t)(b * SQ) * DM + h * DKH;
    const int*   mrow = mask + b * SQ;

    // Load Q tile (32 x 64)
#pragma unroll
    for (int i = 0; i < 2; i++) {
        int idx = tid + i * 256;
        int r = idx >> 4, cc = (idx & 15) * 4;
        *(float4*)&Qs[r * 64 + cc] =
            *(const float4*)(Qg + (size_t)(q0 + r) * DM + cc);
    }

    float mrun[4][2], lrun[4][2];
    u64 Un[4][2][4];   // packed over n parity (lo=even n, hi=odd n)
#pragma unroll
    for (int ch = 0; ch < 4; ch++)
#pragma unroll
        for (int im = 0; im < 2; im++) {
            mrun[ch][im] = -1e30f;
            lrun[ch][im] = 0.f;
#pragma unroll
            for (int j = 0; j < 4; j++) Un[ch][im][j] = 0ull;
        }

    for (int n0 = 0; n0 < SQ; n0 += 64) {
        __syncthreads();
        // Load K (stride-66 rows) and V tiles (64 x 64)
#pragma unroll
        for (int i = 0; i < 4; i++) {
            int idx = tid + i * 256;
            int r = idx >> 4, cc = (idx & 15) * 4;
            float4 k4 = *(const float4*)(Kg + (size_t)(n0 + r) * DM + cc);
            *(float2*)&Ks[r * KS_STRIDE + cc]     = make_float2(k4.x, k4.y);
            *(float2*)&Ks[r * KS_STRIDE + cc + 2] = make_float2(k4.z, k4.w);
            *(float4*)&Vs[r * 64 + cc] =
                *(const float4*)(Vg + (size_t)(n0 + r) * DM + cc);
        }
        __syncthreads();

        // ---- Scores: packed over t-pairs ----
        u64 scp[4][2][4];
#pragma unroll
        for (int ch = 0; ch < 4; ch++)
#pragma unroll
            for (int im = 0; im < 2; im++)
#pragma unroll
                for (int in = 0; in < 4; in++) scp[ch][im][in] = 0ull;

#pragma unroll 2
        for (int t2 = 0; t2 < 16; t2 += 2) {
            u64 q[2][4], nqx[2], nqy[2], nqz[2];
#pragma unroll
            for (int im = 0; im < 2; im++) {
#pragma unroll
                for (int ch = 0; ch < 4; ch++)
                    q[im][ch] = *(const u64*)&Qs[(ty*2+im)*64 + ch*16 + t2];
                NEG2(nqx[im], q[im][1]);
                NEG2(nqy[im], q[im][2]);
                NEG2(nqz[im], q[im][3]);
            }
#pragma unroll
            for (int in = 0; in < 4; in++) {
                int row = in * 16 + tx;
                u64 kr = *(const u64*)&Ks[row*KS_STRIDE + 0*16 + t2];
                u64 kx = *(const u64*)&Ks[row*KS_STRIDE + 1*16 + t2];
                u64 ky = *(const u64*)&Ks[row*KS_STRIDE + 2*16 + t2];
                u64 kz = *(const u64*)&Ks[row*KS_STRIDE + 3*16 + t2];
#pragma unroll
                for (int im = 0; im < 2; im++) {
                    u64 qr = q[im][0], qx = q[im][1], qy = q[im][2], qz = q[im][3];
                    FMA2(scp[0][im][in], qr,     kr, scp[0][im][in]);
                    FMA2(scp[0][im][in], nqx[im],kx, scp[0][im][in]);
                    FMA2(scp[0][im][in], nqy[im],ky, scp[0][im][in]);
                    FMA2(scp[0][im][in], nqz[im],kz, scp[0][im][in]);
                    FMA2(scp[1][im][in], qr,     kx, scp[1][im][in]);
                    FMA2(scp[1][im][in], qx,     kr, scp[1][im][in]);
                    FMA2(scp[1][im][in], qy,     kz, scp[1][im][in]);
                    FMA2(scp[1][im][in], nqz[im],ky, scp[1][im][in]);
                    FMA2(scp[2][im][in], qr,     ky, scp[2][im][in]);
                    FMA2(scp[2][im][in], nqx[im],kz, scp[2][im][in]);
                    FMA2(scp[2][im][in], qy,     kr, scp[2][im][in]);
                    FMA2(scp[2][im][in], qz,     kx, scp[2][im][in]);
                    FMA2(scp[3][im][in], qr,     kz, scp[3][im][in]);
                    FMA2(scp[3][im][in], qx,     ky, scp[3][im][in]);
                    FMA2(scp[3][im][in], nqy[im],kx, scp[3][im][in]);
                    FMA2(scp[3][im][in], qz,     kr, scp[3][im][in]);
                }
            }
        }

        // ---- Mask + per-channel online softmax ----
        int mk[4];
#pragma unroll
        for (int in = 0; in < 4; in++) mk[in] = mrow[n0 + in*16 + tx];

#pragma unroll
        for (int ch = 0; ch < 4; ch++) {
#pragma unroll
            for (int im = 0; im < 2; im++) {
                float s[4];
#pragma unroll
                for (int in = 0; in < 4; in++) {
                    float lo, hi;
                    UNPACK2(lo, hi, scp[ch][im][in]);
                    float v = (lo + hi) * 0.125f;   // 1/sqrt(64)
                    s[in] = mk[in] ? v : -1e9f;
                }
                float tmax = fmaxf(fmaxf(s[0], s[1]), fmaxf(s[2], s[3]));
#pragma unroll
                for (int off = 8; off > 0; off >>= 1)
                    tmax = fmaxf(tmax, __shfl_xor_sync(0xffffffffu, tmax, off));
                float mnew = fmaxf(mrun[ch][im], tmax);
                float corr = __expf(mrun[ch][im] - mnew);
                float p[4], ps = 0.f;
#pragma unroll
                for (int in = 0; in < 4; in++) { p[in] = __expf(s[in] - mnew); ps += p[in]; }
#pragma unroll
                for (int off = 8; off > 0; off >>= 1)
                    ps += __shfl_xor_sync(0xffffffffu, ps, off);
                lrun[ch][im] = lrun[ch][im] * corr + ps;
                mrun[ch][im] = mnew;
                u64 cp;
                PACK2(cp, corr, corr);
#pragma unroll
                for (int j = 0; j < 4; j++) MUL2(Un[ch][im][j], Un[ch][im][j], cp);
                float* prow = &Ps[ch * 2048 + (ty*2+im) * 64];
#pragma unroll
                for (int in = 0; in < 4; in++) prow[in*16 + tx] = p[in];
            }
        }
        __syncthreads();

        // ---- P @ V accumulation, packed over n-pairs ----
#pragma unroll 4
        for (int n2 = 0; n2 < 64; n2 += 2) {
            float4 v0 = *(float4*)&Vs[n2 * 64 + tx * 4];
            float4 v1 = *(float4*)&Vs[(n2+1) * 64 + tx * 4];
            u64 vp[4];
            PACK2(vp[0], v0.x, v1.x);
            PACK2(vp[1], v0.y, v1.y);
            PACK2(vp[2], v0.z, v1.z);
            PACK2(vp[3], v0.w, v1.w);
#pragma unroll
            for (int ch = 0; ch < 4; ch++)
#pragma unroll
                for (int im = 0; im < 2; im++) {
                    u64 p2 = *(const u64*)&Ps[ch * 2048 + (ty*2+im) * 64 + n2];
#pragma unroll
                    for (int j = 0; j < 4; j++)
                        FMA2(Un[ch][im][j], p2, vp[j], Un[ch][im][j]);
                }
        }
    }

    __syncthreads();
    // Normalize A_c = (Un.lo + Un.hi) / l_c into Ps region
#pragma unroll
    for (int ch = 0; ch < 4; ch++)
#pragma unroll
        for (int im = 0; im < 2; im++) {
            float inv = 1.f / lrun[ch][im];
            float u[4];
#pragma unroll
            for (int j = 0; j < 4; j++) {
                float lo, hi;
                UNPACK2(lo, hi, Un[ch][im][j]);
                u[j] = (lo + hi) * inv;
            }
            *(float4*)&Ps[ch * 2048 + (ty*2+im) * 64 + tx * 4] =
                make_float4(u[0], u[1], u[2], u[3]);
        }
    __syncthreads();

    // Quaternion combine + write
    float* Og = g_O + (size_t)(b * SQ) * DM + h * DKH;
#pragma unroll
    for (int im = 0; im < 2; im++) {
        int m = ty * 2 + im;
#pragma unroll
        for (int j = 0; j < 4; j++) {
            int col = tx * 4 + j;
            int oc = col >> 4, u = col & 15;
            float o = 0.f;
#pragma unroll
            for (int ch = 0; ch < 4; ch++)
                o += c_SGN[ch * 4 + oc] *
                     Ps[ch * 2048 + m * 64 + c_SRC[ch * 4 + oc] * 16 + u];
            Og[(size_t)(q0 + m) * DM + col] = o;
        }
    }
}

// ---------------------------------------------------------------------------
extern "C" void kernel_launch(void* const* d_in, const int* in_sizes, int n_in,
                              void* d_out, int out_size)
{
    (void)in_sizes; (void)n_in; (void)out_size;
    // metadata order: 0 q, 1 k, 2 v, 3 mask, 4-19 weights (wq_*, wk_*, wv_*, wo_*),
    // 20 bq, 21 bk, 22 bv, 23 bo
    WPtrs wp;
    for (int i = 0; i < 16; i++) wp.w[i] = (const float*)d_in[4 + i];

    build_wbig_kernel<<<(4 * DM * DM) / 256, 256>>>(wp);

    GemmArgs ga;
    for (int z = 0; z < 3; z++) {
        ga.A[z]    = (const float*)d_in[z];
        ga.bias[z] = (const float*)d_in[20 + z];
    }
    dim3 qkvgrid(DM / 128, MROWS / 128, 3);   // (8, 16, 3)
    qkv_gemm_kernel<<<qkvgrid, 256>>>(ga);

    int smem = ATT_SMEM_FLOATS * 4;
    cudaFuncSetAttribute(quat_attn_kernel,
                         cudaFuncAttributeMaxDynamicSharedMemorySize, smem);
    quat_attn_kernel<<<dim3(SQ / 32, BSZ * NH), 256, smem>>>((const int*)d_in[3]);

    dim3 ogrid(DM / 128, MROWS / 128);        // (8, 16)
    o_gemm_kernel<<<ogrid, 256>>>((const float*)d_in[23], (float*)d_out);
}

// round 5
// speedup vs baseline: 1.1337x; 1.1337x over previous
#include <cuda_runtime.h>
#include <cuda_bf16.h>
#include <cstdint>
#include <math.h>

// Problem constants
#define SQ   1024
#define DM   1024
#define NH   16
#define DKH  64
#define BSZ  2
#define MROWS (BSZ*SQ)

// ---------------------------------------------------------------------------
// Device scratch (allocation-free per harness rules)
// ---------------------------------------------------------------------------
__device__ __nv_bfloat16 g_Wth[4][DM*DM];  // W^T hi (K-major: [n][k]), 8 MB
__device__ __nv_bfloat16 g_Wtl[4][DM*DM];  // W^T lo, 8 MB
__device__ float g_P[3][MROWS*DM];         // projected Q,K,V, 24 MB
__device__ float g_O[MROWS*DM];            // attention output, 8 MB

__constant__ int   c_SRC[16] = {0,1,2,3,  1,0,3,2,  2,3,0,1,  3,2,1,0};
__constant__ float c_SGN[16] = {1.f,1.f,1.f,1.f,  -1.f,1.f,-1.f,1.f,
                                -1.f,1.f,1.f,-1.f, -1.f,-1.f,1.f,1.f};

struct WPtrs { const float* w[16]; };
struct GemmArgs { const float* A[3]; const float* bias[3]; };

// pack two f32 -> bf16x2 (lo half = flo, hi half = fhi)
#define BFPACK(r, flo, fhi) \
    asm("cvt.rn.bf16x2.f32 %0, %1, %2;" : "=r"(r) : "f"(fhi), "f"(flo))

// m16n8k16 row.col bf16 MMA, fp32 accumulate (sm_80+, works on plain sm_103)
#define HMMA(c, a0, a1, a2, a3, b0, b1) \
    asm volatile("mma.sync.aligned.m16n8k16.row.col.f32.bf16.bf16.f32 " \
        "{%0,%1,%2,%3}, {%4,%5,%6,%7}, {%8,%9}, {%0,%1,%2,%3};" \
        : "+f"((c)[0]), "+f"((c)[1]), "+f"((c)[2]), "+f"((c)[3]) \
        : "r"(a0), "r"(a1), "r"(a2), "r"(a3), "r"(b0), "r"(b1))

// ---------------------------------------------------------------------------
// Build transposed + bf16-split quaternion weight matrices.
// g_Wt*[which][n*1024+k] = split of SGN[rb][cb] * w_src[k%256][n%256]
// ---------------------------------------------------------------------------
__global__ __launch_bounds__(256)
void build_wbig_kernel(WPtrs p) {
    __shared__ float s[32][33];
    int tx = threadIdx.x & 31, ty = threadIdx.x >> 5;
    int k0 = blockIdx.x * 32, n0 = blockIdx.y * 32, which = blockIdx.z;
    int rb = k0 >> 8, cb = n0 >> 8;
    float sgn = c_SGN[rb * 4 + cb];
    const float* src = p.w[which * 4 + c_SRC[rb * 4 + cb]];
#pragma unroll
    for (int i = 0; i < 4; i++) {
        int kl = ty + i * 8;
        s[kl][tx] = sgn * src[((k0 + kl) & 255) * 256 + ((n0 + tx) & 255)];
    }
    __syncthreads();
#pragma unroll
    for (int i = 0; i < 4; i++) {
        int nl = ty + i * 8;
        float v = s[tx][nl];
        __nv_bfloat16 hi = __float2bfloat16_rn(v);
        __nv_bfloat16 lo = __float2bfloat16_rn(v - __bfloat162float(hi));
        size_t o = (size_t)(n0 + nl) * DM + k0 + tx;
        g_Wth[which][o] = hi;
        g_Wtl[which][o] = lo;
    }
}

// ---------------------------------------------------------------------------
// Tensor-core GEMM via mma.sync: C[128x128 tile] = A(fp32) @ W + bias.
// 3-term bf16 split: Ahi*Whi + Ahi*Wlo + Alo*Whi, fp32 accum.
// 256 threads = 8 warps, 2(m) x 4(n); warp tile 64x32; k-chunk 32.
// ---------------------------------------------------------------------------
#define KCP 40   // smem k-stride in bf16 elements (80B = 20 banks: conflict-free)

__device__ __forceinline__
void tc_gemm_body(const float* __restrict__ A,
                  const __nv_bfloat16* __restrict__ Wh,
                  const __nv_bfloat16* __restrict__ Wl,
                  const float* __restrict__ bias, float* __restrict__ C)
{
    __shared__ __nv_bfloat16 Ah_s[128 * KCP];
    __shared__ __nv_bfloat16 Al_s[128 * KCP];
    __shared__ __nv_bfloat16 Wh_s[128 * KCP];
    __shared__ __nv_bfloat16 Wl_s[128 * KCP];

    int tid = threadIdx.x;
    int wid = tid >> 5, lane = tid & 31;
    int gid = lane >> 2, tig = lane & 3;
    int wm = wid & 1, wn = wid >> 1;         // warp coords: 2 x 4
    int m0 = blockIdx.y * 128, n0 = blockIdx.x * 128;

    float acc[4][4][4];
#pragma unroll
    for (int mi = 0; mi < 4; mi++)
#pragma unroll
        for (int ni = 0; ni < 4; ni++)
#pragma unroll
            for (int j = 0; j < 4; j++) acc[mi][ni][j] = 0.f;

    for (int k0 = 0; k0 < DM; k0 += 32) {
        __syncthreads();
        // A: 128x32 fp32 -> bf16 hi/lo. 1024 float4 total, 4/thread.
        const float* Ar = A + (size_t)m0 * DM + k0;
#pragma unroll
        for (int i = 0; i < 4; i++) {
            int idx = tid + i * 256;
            int r = idx >> 3, c4 = (idx & 7) * 4;
            float4 a = *(const float4*)(Ar + (size_t)r * DM + c4);
            uint32_t h01, h23, l01, l23;
            BFPACK(h01, a.x, a.y);
            BFPACK(h23, a.z, a.w);
            float rx = a.x - __uint_as_float(h01 << 16);
            float ry = a.y - __uint_as_float(h01 & 0xffff0000u);
            float rz = a.z - __uint_as_float(h23 << 16);
            float rw = a.w - __uint_as_float(h23 & 0xffff0000u);
            BFPACK(l01, rx, ry);
            BFPACK(l23, rz, rw);
            int so = r * KCP + c4;
            *(uint2*)(Ah_s + so) = make_uint2(h01, h23);
            *(uint2*)(Al_s + so) = make_uint2(l01, l23);
        }
        // W: 128(n) x 32(k) bf16 hi/lo. 512 uint4 each, 2/thread.
#pragma unroll
        for (int i = 0; i < 2; i++) {
            int idx = tid + i * 256;
            int r = idx >> 2, c8 = (idx & 3) * 8;
            size_t go = (size_t)(n0 + r) * DM + k0 + c8;
            int so = r * KCP + c8;
            *(uint4*)(Wh_s + so) = *(const uint4*)(Wh + go);
            *(uint4*)(Wl_s + so) = *(const uint4*)(Wl + go);
        }
        __syncthreads();

#pragma unroll
        for (int ks = 0; ks < 2; ks++) {
            int kb = ks * 16 + tig * 2;
            // B fragments for 4 n-tiles (hi & lo)
            uint32_t bh[4][2], bl[4][2];
#pragma unroll
            for (int ni = 0; ni < 4; ni++) {
                int n = wn * 32 + ni * 8 + gid;
                int off = n * KCP + kb;
                bh[ni][0] = *(const uint32_t*)(Wh_s + off);
                bh[ni][1] = *(const uint32_t*)(Wh_s + off + 8);
                bl[ni][0] = *(const uint32_t*)(Wl_s + off);
                bl[ni][1] = *(const uint32_t*)(Wl_s + off + 8);
            }
#pragma unroll
            for (int mi = 0; mi < 4; mi++) {
                int r = wm * 64 + mi * 16 + gid;
                int off = r * KCP + kb;
                uint32_t ah0 = *(const uint32_t*)(Ah_s + off);
                uint32_t ah1 = *(const uint32_t*)(Ah_s + off + 8 * KCP);
                uint32_t ah2 = *(const uint32_t*)(Ah_s + off + 8);
                uint32_t ah3 = *(const uint32_t*)(Ah_s + off + 8 * KCP + 8);
                uint32_t al0 = *(const uint32_t*)(Al_s + off);
                uint32_t al1 = *(const uint32_t*)(Al_s + off + 8 * KCP);
                uint32_t al2 = *(const uint32_t*)(Al_s + off + 8);
                uint32_t al3 = *(const uint32_t*)(Al_s + off + 8 * KCP + 8);
#pragma unroll
                for (int ni = 0; ni < 4; ni++) {
                    HMMA(acc[mi][ni], ah0, ah1, ah2, ah3, bh[ni][0], bh[ni][1]);
                    HMMA(acc[mi][ni], ah0, ah1, ah2, ah3, bl[ni][0], bl[ni][1]);
                    HMMA(acc[mi][ni], al0, al1, al2, al3, bh[ni][0], bh[ni][1]);
                }
            }
        }
    }

    // Epilogue: D layout: c0,c1 -> (row gid, col tig*2, tig*2+1); c2,c3 -> row gid+8
#pragma unroll
    for (int mi = 0; mi < 4; mi++) {
        int r = m0 + wm * 64 + mi * 16 + gid;
#pragma unroll
        for (int ni = 0; ni < 4; ni++) {
            int c = n0 + wn * 32 + ni * 8 + tig * 2;
            float b0 = bias[c], b1 = bias[c + 1];
            *(float2*)(C + (size_t)r * DM + c) =
                make_float2(acc[mi][ni][0] + b0, acc[mi][ni][1] + b1);
            *(float2*)(C + (size_t)(r + 8) * DM + c) =
                make_float2(acc[mi][ni][2] + b0, acc[mi][ni][3] + b1);
        }
    }
}

__global__ __launch_bounds__(256)
void qkv_gemm_kernel(GemmArgs args) {
    int z = blockIdx.z;
    tc_gemm_body(args.A[z], g_Wth[z], g_Wtl[z], args.bias[z], g_P[z]);
}
__global__ __launch_bounds__(256)
void o_gemm_kernel(const float* __restrict__ bias, float* __restrict__ Cout) {
    tc_gemm_body(g_O, g_Wth[3], g_Wtl[3], bias, Cout);
}

// ---------------------------------------------------------------------------
// Quaternion flash attention (R2 scalar version, unchanged).
// ---------------------------------------------------------------------------
#define ATT_SMEM_FLOATS (2048 + 4160 + 4096 + 8192)

__global__ __launch_bounds__(256)
void quat_attn_kernel(const int* __restrict__ mask)
{
    extern __shared__ float smemf[];
    float* Qs = smemf;                      // [32][64]
    float* Ks = smemf + 2048;               // [64][65] padded
    float* Vs = smemf + 2048 + 4160;        // [64][64]
    float* Ps = smemf + 2048 + 4160 + 4096; // [4][32][64]

    int tid = threadIdx.x;
    int tx = tid & 15, ty = tid >> 4;
    int bh = blockIdx.y;
    int b = bh >> 4, h = bh & 15;
    int q0 = blockIdx.x * 32;

    const float* Qg = g_P[0] + (size_t)(b * SQ) * DM + h * DKH;
    const float* Kg = g_P[1] + (size_t)(b * SQ) * DM + h * DKH;
    const float* Vg = g_P[2] + (size_t)(b * SQ) * DM + h * DKH;
    const int*   mrow = mask + b * SQ;

#pragma unroll
    for (int i = 0; i < 2; i++) {
        int idx = tid + i * 256;
        int r = idx >> 4, cc = (idx & 15) * 4;
        *(float4*)&Qs[r * 64 + cc] =
            *(const float4*)(Qg + (size_t)(q0 + r) * DM + cc);
    }

    float mrun[4][2], lrun[4][2], U[4][2][4];
#pragma unroll
    for (int ch = 0; ch < 4; ch++)
#pragma unroll
        for (int im = 0; im < 2; im++) {
            mrun[ch][im] = -1e30f;
            lrun[ch][im] = 0.f;
#pragma unroll
            for (int j = 0; j < 4; j++) U[ch][im][j] = 0.f;
        }

    for (int n0 = 0; n0 < SQ; n0 += 64) {
        __syncthreads();
#pragma unroll
        for (int i = 0; i < 4; i++) {
            int idx = tid + i * 256;
            int r = idx >> 4, cc = (idx & 15) * 4;
            float4 k4 = *(const float4*)(Kg + (size_t)(n0 + r) * DM + cc);
            Ks[r * 65 + cc + 0] = k4.x; Ks[r * 65 + cc + 1] = k4.y;
            Ks[r * 65 + cc + 2] = k4.z; Ks[r * 65 + cc + 3] = k4.w;
            *(float4*)&Vs[r * 64 + cc] =
                *(const float4*)(Vg + (size_t)(n0 + r) * DM + cc);
        }
        __syncthreads();

        float sc[4][2][4];
#pragma unroll
        for (int ch = 0; ch < 4; ch++)
#pragma unroll
            for (int im = 0; im < 2; im++)
#pragma unroll
                for (int in = 0; in < 4; in++) sc[ch][im][in] = 0.f;

#pragma unroll 4
        for (int t = 0; t < 16; t++) {
            float qv[2][4], kv[4][4];
#pragma unroll
            for (int im = 0; im < 2; im++)
#pragma unroll
                for (int ch = 0; ch < 4; ch++)
                    qv[im][ch] = Qs[(ty * 2 + im) * 64 + ch * 16 + t];
#pragma unroll
            for (int in = 0; in < 4; in++)
#pragma unroll
                for (int ch = 0; ch < 4; ch++)
                    kv[in][ch] = Ks[(tx * 4 + in) * 65 + ch * 16 + t];
#pragma unroll
            for (int im = 0; im < 2; im++) {
                float ar = qv[im][0], ax = qv[im][1], ay = qv[im][2], az = qv[im][3];
#pragma unroll
                for (int in = 0; in < 4; in++) {
                    float br = kv[in][0], bx = kv[in][1], by = kv[in][2], bz = kv[in][3];
                    sc[0][im][in] += ar * br - ax * bx - ay * by - az * bz;
                    sc[1][im][in] += ar * bx + ax * br + ay * bz - az * by;
                    sc[2][im][in] += ar * by - ax * bz + ay * br + az * bx;
                    sc[3][im][in] += ar * bz + ax * by - ay * bx + az * br;
                }
            }
        }

        int mk[4];
#pragma unroll
        for (int in = 0; in < 4; in++) mk[in] = mrow[n0 + tx * 4 + in];

#pragma unroll
        for (int ch = 0; ch < 4; ch++) {
#pragma unroll
            for (int im = 0; im < 2; im++) {
                float s[4];
#pragma unroll
                for (int in = 0; in < 4; in++) {
                    float v = sc[ch][im][in] * 0.125f;
                    s[in] = mk[in] ? v : -1e9f;
                }
                float tmax = fmaxf(fmaxf(s[0], s[1]), fmaxf(s[2], s[3]));
#pragma unroll
                for (int off = 8; off > 0; off >>= 1)
                    tmax = fmaxf(tmax, __shfl_xor_sync(0xffffffffu, tmax, off));
                float mnew = fmaxf(mrun[ch][im], tmax);
                float corr = __expf(mrun[ch][im] - mnew);
                float p[4], ps = 0.f;
#pragma unroll
                for (int in = 0; in < 4; in++) { p[in] = __expf(s[in] - mnew); ps += p[in]; }
#pragma unroll
                for (int off = 8; off > 0; off >>= 1)
                    ps += __shfl_xor_sync(0xffffffffu, ps, off);
                lrun[ch][im] = lrun[ch][im] * corr + ps;
                mrun[ch][im] = mnew;
#pragma unroll
                for (int j = 0; j < 4; j++) U[ch][im][j] *= corr;
                *(float4*)&Ps[ch * 2048 + (ty * 2 + im) * 64 + tx * 4] =
                    make_float4(p[0], p[1], p[2], p[3]);
            }
        }
        __syncthreads();

#pragma unroll 8
        for (int n = 0; n < 64; n++) {
            float4 v = *(float4*)&Vs[n * 64 + tx * 4];
#pragma unroll
            for (int ch = 0; ch < 4; ch++)
#pragma unroll
                for (int im = 0; im < 2; im++) {
                    float p = Ps[ch * 2048 + (ty * 2 + im) * 64 + n];
                    U[ch][im][0] += p * v.x;
                    U[ch][im][1] += p * v.y;
                    U[ch][im][2] += p * v.z;
                    U[ch][im][3] += p * v.w;
                }
        }
    }

    __syncthreads();
#pragma unroll
    for (int ch = 0; ch < 4; ch++)
#pragma unroll
        for (int im = 0; im < 2; im++) {
            float inv = 1.f / lrun[ch][im];
            *(float4*)&Ps[ch * 2048 + (ty * 2 + im) * 64 + tx * 4] =
                make_float4(U[ch][im][0] * inv, U[ch][im][1] * inv,
                            U[ch][im][2] * inv, U[ch][im][3] * inv);
        }
    __syncthreads();

    float* Og = g_O + (size_t)(b * SQ) * DM + h * DKH;
#pragma unroll
    for (int im = 0; im < 2; im++) {
        int m = ty * 2 + im;
#pragma unroll
        for (int j = 0; j < 4; j++) {
            int col = tx * 4 + j;
            int oc = col >> 4, u = col & 15;
            float o = 0.f;
#pragma unroll
            for (int ch = 0; ch < 4; ch++)
                o += c_SGN[ch * 4 + oc] *
                     Ps[ch * 2048 + m * 64 + c_SRC[ch * 4 + oc] * 16 + u];
            Og[(size_t)(q0 + m) * DM + col] = o;
        }
    }
}

// ---------------------------------------------------------------------------
extern "C" void kernel_launch(void* const* d_in, const int* in_sizes, int n_in,
                              void* d_out, int out_size)
{
    (void)in_sizes; (void)n_in; (void)out_size;
    // metadata order: 0 q, 1 k, 2 v, 3 mask, 4-19 weights (wq_*, wk_*, wv_*, wo_*),
    // 20 bq, 21 bk, 22 bv, 23 bo
    WPtrs wp;
    for (int i = 0; i < 16; i++) wp.w[i] = (const float*)d_in[4 + i];

    build_wbig_kernel<<<dim3(32, 32, 4), 256>>>(wp);

    GemmArgs ga;
    for (int z = 0; z < 3; z++) {
        ga.A[z]    = (const float*)d_in[z];
        ga.bias[z] = (const float*)d_in[20 + z];
    }
    dim3 qkvgrid(DM / 128, MROWS / 128, 3);   // (8, 16, 3)
    qkv_gemm_kernel<<<qkvgrid, 256>>>(ga);

    int smem = ATT_SMEM_FLOATS * 4;
    cudaFuncSetAttribute(quat_attn_kernel,
                         cudaFuncAttributeMaxDynamicSharedMemorySize, smem);
    quat_attn_kernel<<<dim3(SQ / 32, BSZ * NH), 256, smem>>>((const int*)d_in[3]);

    dim3 ogrid(DM / 128, MROWS / 128);        // (8, 16)
    o_gemm_kernel<<<ogrid, 256>>>((const float*)d_in[23], (float*)d_out);
}

// round 8
// speedup vs baseline: 2.0330x; 1.7933x over previous
#include <cuda_runtime.h>
#include <cuda_bf16.h>
#include <cstdint>
#include <math.h>

#define SQ   1024
#define DM   1024
#define NH   16
#define DKH  64
#define BSZ  2
#define MROWS (BSZ*SQ)

typedef uint32_t u32;

// ---------------------------------------------------------------------------
// Device scratch
// ---------------------------------------------------------------------------
__device__ __nv_bfloat16 g_Wth[4][DM*DM];  // W^T hi (K-major [n][k])
__device__ __nv_bfloat16 g_Wtl[4][DM*DM];  // W^T lo
__device__ float g_P[2][MROWS*DM];         // projected Q,K
__device__ float g_Vt[BSZ*NH*DKH*SQ];      // projected V, transposed [b,h,d,S]
__device__ float g_O[MROWS*DM];            // attention output

__constant__ int   c_SRC[16] = {0,1,2,3,  1,0,3,2,  2,3,0,1,  3,2,1,0};
__constant__ float c_SGN[16] = {1.f,1.f,1.f,1.f,  -1.f,1.f,-1.f,1.f,
                                -1.f,1.f,1.f,-1.f, -1.f,-1.f,1.f,1.f};

struct WPtrs { const float* w[16]; };
struct GemmArgs { const float* A[3]; const float* bias[3]; };

#define BFPACK(r, flo, fhi) \
    asm("cvt.rn.bf16x2.f32 %0, %1, %2;" : "=r"(r) : "f"(fhi), "f"(flo))

#define HMMA(c, a0, a1, a2, a3, b0, b1) \
    asm volatile("mma.sync.aligned.m16n8k16.row.col.f32.bf16.bf16.f32 " \
        "{%0,%1,%2,%3}, {%4,%5,%6,%7}, {%8,%9}, {%0,%1,%2,%3};" \
        : "+f"((c)[0]), "+f"((c)[1]), "+f"((c)[2]), "+f"((c)[3]) \
        : "r"(a0), "r"(a1), "r"(a2), "r"(a3), "r"(b0), "r"(b1))

#define SGNM 0x80008000u

// ---------------------------------------------------------------------------
__global__ __launch_bounds__(256)
void build_wbig_kernel(WPtrs p) {
    __shared__ float s[32][33];
    int tx = threadIdx.x & 31, ty = threadIdx.x >> 5;
    int k0 = blockIdx.x * 32, n0 = blockIdx.y * 32, which = blockIdx.z;
    int rb = k0 >> 8, cb = n0 >> 8;
    float sgn = c_SGN[rb * 4 + cb];
    const float* src = p.w[which * 4 + c_SRC[rb * 4 + cb]];
#pragma unroll
    for (int i = 0; i < 4; i++) {
        int kl = ty + i * 8;
        s[kl][tx] = sgn * src[((k0 + kl) & 255) * 256 + ((n0 + tx) & 255)];
    }
    __syncthreads();
#pragma unroll
    for (int i = 0; i < 4; i++) {
        int nl = ty + i * 8;
        float v = s[tx][nl];
        __nv_bfloat16 hi = __float2bfloat16_rn(v);
        __nv_bfloat16 lo = __float2bfloat16_rn(v - __bfloat162float(hi));
        size_t o = (size_t)(n0 + nl) * DM + k0 + tx;
        g_Wth[which][o] = hi;
        g_Wtl[which][o] = lo;
    }
}

// ---------------------------------------------------------------------------
// Tensor-core GEMM (validated). vt!=0: write V output transposed to g_Vt.
// ---------------------------------------------------------------------------
#define KCP 40

__device__ __forceinline__
void tc_gemm_body(const float* __restrict__ A,
                  const __nv_bfloat16* __restrict__ Wh,
                  const __nv_bfloat16* __restrict__ Wl,
                  const float* __restrict__ bias, float* __restrict__ C, int vt)
{
    __shared__ __nv_bfloat16 Ah_s[128 * KCP];
    __shared__ __nv_bfloat16 Al_s[128 * KCP];
    __shared__ __nv_bfloat16 Wh_s[128 * KCP];
    __shared__ __nv_bfloat16 Wl_s[128 * KCP];

    int tid = threadIdx.x;
    int wid = tid >> 5, lane = tid & 31;
    int gid = lane >> 2, tig = lane & 3;
    int wm = wid & 1, wn = wid >> 1;
    int m0 = blockIdx.y * 128, n0 = blockIdx.x * 128;

    float acc[4][4][4];
#pragma unroll
    for (int mi = 0; mi < 4; mi++)
#pragma unroll
        for (int ni = 0; ni < 4; ni++)
#pragma unroll
            for (int j = 0; j < 4; j++) acc[mi][ni][j] = 0.f;

    for (int k0 = 0; k0 < DM; k0 += 32) {
        __syncthreads();
        const float* Ar = A + (size_t)m0 * DM + k0;
#pragma unroll
        for (int i = 0; i < 4; i++) {
            int idx = tid + i * 256;
            int r = idx >> 3, c4 = (idx & 7) * 4;
            float4 a = *(const float4*)(Ar + (size_t)r * DM + c4);
            u32 h01, h23, l01, l23;
            BFPACK(h01, a.x, a.y);
            BFPACK(h23, a.z, a.w);
            float rx = a.x - __uint_as_float(h01 << 16);
            float ry = a.y - __uint_as_float(h01 & 0xffff0000u);
            float rz = a.z - __uint_as_float(h23 << 16);
            float rw = a.w - __uint_as_float(h23 & 0xffff0000u);
            BFPACK(l01, rx, ry);
            BFPACK(l23, rz, rw);
            int so = r * KCP + c4;
            *(uint2*)(Ah_s + so) = make_uint2(h01, h23);
            *(uint2*)(Al_s + so) = make_uint2(l01, l23);
        }
#pragma unroll
        for (int i = 0; i < 2; i++) {
            int idx = tid + i * 256;
            int r = idx >> 2, c8 = (idx & 3) * 8;
            size_t go = (size_t)(n0 + r) * DM + k0 + c8;
            int so = r * KCP + c8;
            *(uint4*)(Wh_s + so) = *(const uint4*)(Wh + go);
            *(uint4*)(Wl_s + so) = *(const uint4*)(Wl + go);
        }
        __syncthreads();

#pragma unroll
        for (int ks = 0; ks < 2; ks++) {
            int kb = ks * 16 + tig * 2;
            u32 bh[4][2], bl[4][2];
#pragma unroll
            for (int ni = 0; ni < 4; ni++) {
                int n = wn * 32 + ni * 8 + gid;
                int off = n * KCP + kb;
                bh[ni][0] = *(const u32*)(Wh_s + off);
                bh[ni][1] = *(const u32*)(Wh_s + off + 8);
                bl[ni][0] = *(const u32*)(Wl_s + off);
                bl[ni][1] = *(const u32*)(Wl_s + off + 8);
            }
#pragma unroll
            for (int mi = 0; mi < 4; mi++) {
                int r = wm * 64 + mi * 16 + gid;
                int off = r * KCP + kb;
                u32 ah0 = *(const u32*)(Ah_s + off);
                u32 ah1 = *(const u32*)(Ah_s + off + 8 * KCP);
                u32 ah2 = *(const u32*)(Ah_s + off + 8);
                u32 ah3 = *(const u32*)(Ah_s + off + 8 * KCP + 8);
                u32 al0 = *(const u32*)(Al_s + off);
                u32 al1 = *(const u32*)(Al_s + off + 8 * KCP);
                u32 al2 = *(const u32*)(Al_s + off + 8);
                u32 al3 = *(const u32*)(Al_s + off + 8 * KCP + 8);
#pragma unroll
                for (int ni = 0; ni < 4; ni++) {
                    HMMA(acc[mi][ni], ah0, ah1, ah2, ah3, bh[ni][0], bh[ni][1]);
                    HMMA(acc[mi][ni], ah0, ah1, ah2, ah3, bl[ni][0], bl[ni][1]);
                    HMMA(acc[mi][ni], al0, al1, al2, al3, bh[ni][0], bh[ni][1]);
                }
            }
        }
    }

#pragma unroll
    for (int mi = 0; mi < 4; mi++) {
        int r = m0 + wm * 64 + mi * 16 + gid;
#pragma unroll
        for (int ni = 0; ni < 4; ni++) {
            int c = n0 + wn * 32 + ni * 8 + tig * 2;
            float b0 = bias[c], b1 = bias[c + 1];
            if (!vt) {
                *(float2*)(C + (size_t)r * DM + c) =
                    make_float2(acc[mi][ni][0] + b0, acc[mi][ni][1] + b1);
                *(float2*)(C + (size_t)(r + 8) * DM + c) =
                    make_float2(acc[mi][ni][2] + b0, acc[mi][ni][3] + b1);
            } else {
                int b = r >> 10, s = r & 1023;
                int h = c >> 6, d = c & 63;
                float* base = g_Vt + ((size_t)(b * NH + h) * DKH) * SQ;
                base[(size_t)d * SQ + s]           = acc[mi][ni][0] + b0;
                base[(size_t)(d + 1) * SQ + s]     = acc[mi][ni][1] + b1;
                base[(size_t)d * SQ + s + 8]       = acc[mi][ni][2] + b0;
                base[(size_t)(d + 1) * SQ + s + 8] = acc[mi][ni][3] + b1;
            }
        }
    }
}

__global__ __launch_bounds__(256)
void qkv_gemm_kernel(GemmArgs args) {
    int z = blockIdx.z;
    tc_gemm_body(args.A[z], g_Wth[z], g_Wtl[z], args.bias[z],
                 z < 2 ? g_P[z] : nullptr, z == 2);
}
__global__ __launch_bounds__(256)
void o_gemm_kernel(const float* __restrict__ bias, float* __restrict__ Cout) {
    tc_gemm_body(g_O, g_Wth[3], g_Wtl[3], bias, Cout, 0);
}

// ---------------------------------------------------------------------------
// Tensor-core quaternion flash attention.
// Block 256 thr = 8 warps: warp = (mtile 0..3 [16 q rows], wh 0..1 [key/out half]).
// Q block 64 rows; key tiles of 64. 3-term bf16 split everywhere.
// PV applies the output quaternion sign/permutation INSIDE the MMA (B operand =
// signed/permuted V component); the epilogue is therefore a plain sum over the
// four per-channel normalized partials.
// ---------------------------------------------------------------------------
#define STR 72            // bf16 tile row stride (elements)
#define TILE_B (64*STR)   // elements per 64-row tile

#define S_QH  0
#define S_QL  (S_QH + TILE_B)
#define S_KH  (S_QL + TILE_B)
#define S_KL  (S_KH + TILE_B)
#define S_VH  (S_KL + TILE_B)
#define S_VL  (S_VH + TILE_B)
#define S_PH  (S_VL + TILE_B)           // [4][64][STR]
#define S_PL  (S_PH + 4*TILE_B)
#define S_END (S_PL + 4*TILE_B)
#define ATT_SMEM_BYTES (S_END*2 + 2048 + 256)

__global__ __launch_bounds__(256, 1)
void quat_attn_tc_kernel(const int* __restrict__ mask)
{
    extern __shared__ __nv_bfloat16 sm[];
    float* stats = (float*)(sm + S_END);        // [4][64][2]
    int*   msk   = (int*)(stats + 4 * 64 * 2);  // [64]

    // compile-time quaternion tables (folded by ptxas in unrolled code)
    const int tsrc[4][4] = {{0,1,2,3},{1,0,3,2},{2,3,0,1},{3,2,1,0}};
    const int tsgn[4][4] = {{1,1,1,1},{-1,1,-1,1},{-1,1,1,-1},{-1,-1,1,1}};

    int tid = threadIdx.x;
    int wid = tid >> 5, lane = tid & 31;
    int gid = lane >> 2, tig = lane & 3;
    int mtile = wid >> 1, wh = wid & 1;
    int m16 = mtile * 16;
    int bh = blockIdx.y;
    int b = bh >> 4, h = bh & 15;
    int q0 = blockIdx.x * 64;

    const float* Qg = g_P[0] + (size_t)(b * SQ) * DM + h * DKH;
    const float* Kg = g_P[1] + (size_t)(b * SQ) * DM + h * DKH;
    const float* Vg = g_Vt + (size_t)bh * DKH * SQ;
    const int*   mrow = mask + b * SQ;

    // ---- load Q tile (scaled by 1/8), bf16 hi/lo split ----
#pragma unroll
    for (int i = 0; i < 4; i++) {
        int idx = tid + i * 256;
        int r = idx >> 4, c4 = (idx & 15) * 4;
        float4 a = *(const float4*)(Qg + (size_t)(q0 + r) * DM + c4);
        a.x *= 0.125f; a.y *= 0.125f; a.z *= 0.125f; a.w *= 0.125f;
        u32 h01, h23, l01, l23;
        BFPACK(h01, a.x, a.y);
        BFPACK(h23, a.z, a.w);
        float rx = a.x - __uint_as_float(h01 << 16);
        float ry = a.y - __uint_as_float(h01 & 0xffff0000u);
        float rz = a.z - __uint_as_float(h23 << 16);
        float rw = a.w - __uint_as_float(h23 & 0xffff0000u);
        BFPACK(l01, rx, ry);
        BFPACK(l23, rz, rw);
        *(uint2*)(sm + S_QH + r * STR + c4) = make_uint2(h01, h23);
        *(uint2*)(sm + S_QL + r * STR + c4) = make_uint2(l01, l23);
    }
    __syncthreads();

    // ---- persistent Q fragments ----
    u32 qfh[4][4], qfl[4][4];
#pragma unroll
    for (int u = 0; u < 4; u++) {
        int off = (m16 + gid) * STR + u * 16 + tig * 2;
        qfh[u][0] = *(const u32*)(sm + S_QH + off);
        qfh[u][1] = *(const u32*)(sm + S_QH + off + 8 * STR);
        qfh[u][2] = *(const u32*)(sm + S_QH + off + 8);
        qfh[u][3] = *(const u32*)(sm + S_QH + off + 8 * STR + 8);
        qfl[u][0] = *(const u32*)(sm + S_QL + off);
        qfl[u][1] = *(const u32*)(sm + S_QL + off + 8 * STR);
        qfl[u][2] = *(const u32*)(sm + S_QL + off + 8);
        qfl[u][3] = *(const u32*)(sm + S_QL + off + 8 * STR + 8);
    }

    float mrun[4][2], lrun[4][2];
    float U[4][4][4];   // [s-channel][out ntile][frag]
#pragma unroll
    for (int c = 0; c < 4; c++) {
#pragma unroll
        for (int j = 0; j < 2; j++) { mrun[c][j] = -1e30f; lrun[c][j] = 0.f; }
#pragma unroll
        for (int nt = 0; nt < 4; nt++)
#pragma unroll
            for (int j = 0; j < 4; j++) U[c][nt][j] = 0.f;
    }

    for (int n0 = 0; n0 < SQ; n0 += 64) {
        __syncthreads();
        // ---- load K tile and Vt tile, hi/lo split ----
#pragma unroll
        for (int i = 0; i < 4; i++) {
            int idx = tid + i * 256;
            int r = idx >> 4, c4 = (idx & 15) * 4;
            float4 a = *(const float4*)(Kg + (size_t)(n0 + r) * DM + c4);
            u32 h01, h23, l01, l23;
            BFPACK(h01, a.x, a.y);
            BFPACK(h23, a.z, a.w);
            float rx = a.x - __uint_as_float(h01 << 16);
            float ry = a.y - __uint_as_float(h01 & 0xffff0000u);
            float rz = a.z - __uint_as_float(h23 << 16);
            float rw = a.w - __uint_as_float(h23 & 0xffff0000u);
            BFPACK(l01, rx, ry);
            BFPACK(l23, rz, rw);
            *(uint2*)(sm + S_KH + r * STR + c4) = make_uint2(h01, h23);
            *(uint2*)(sm + S_KL + r * STR + c4) = make_uint2(l01, l23);

            float4 v = *(const float4*)(Vg + (size_t)r * SQ + n0 + c4);
            BFPACK(h01, v.x, v.y);
            BFPACK(h23, v.z, v.w);
            rx = v.x - __uint_as_float(h01 << 16);
            ry = v.y - __uint_as_float(h01 & 0xffff0000u);
            rz = v.z - __uint_as_float(h23 << 16);
            rw = v.w - __uint_as_float(h23 & 0xffff0000u);
            BFPACK(l01, rx, ry);
            BFPACK(l23, rz, rw);
            *(uint2*)(sm + S_VH + r * STR + c4) = make_uint2(h01, h23);
            *(uint2*)(sm + S_VL + r * STR + c4) = make_uint2(l01, l23);
        }
        if (tid < 64) msk[tid] = mrow[n0 + tid];
        __syncthreads();

        // ---- score MMAs ----
        float sc[4][4][4];
#pragma unroll
        for (int c = 0; c < 4; c++)
#pragma unroll
            for (int nt = 0; nt < 4; nt++)
#pragma unroll
                for (int j = 0; j < 4; j++) sc[c][nt][j] = 0.f;

#pragma unroll
        for (int nt = 0; nt < 4; nt++) {
            int kb0 = wh * 32 + nt * 8;
            u32 kf[4][2][2];
#pragma unroll
            for (int comp = 0; comp < 4; comp++) {
                int off = (kb0 + gid) * STR + comp * 16 + tig * 2;
                kf[comp][0][0] = *(const u32*)(sm + S_KH + off);
                kf[comp][0][1] = *(const u32*)(sm + S_KH + off + 8);
                kf[comp][1][0] = *(const u32*)(sm + S_KL + off);
                kf[comp][1][1] = *(const u32*)(sm + S_KL + off + 8);
            }
#pragma unroll
            for (int c = 0; c < 4; c++)
#pragma unroll
                for (int u = 0; u < 4; u++) {
                    int src = tsrc[u][c];
                    u32 bh0 = kf[src][0][0], bh1 = kf[src][0][1];
                    u32 bl0 = kf[src][1][0], bl1 = kf[src][1][1];
                    if (tsgn[u][c] < 0) {
                        bh0 ^= SGNM; bh1 ^= SGNM; bl0 ^= SGNM; bl1 ^= SGNM;
                    }
                    HMMA(sc[c][nt], qfh[u][0], qfh[u][1], qfh[u][2], qfh[u][3], bh0, bh1);
                    HMMA(sc[c][nt], qfh[u][0], qfh[u][1], qfh[u][2], qfh[u][3], bl0, bl1);
                    HMMA(sc[c][nt], qfl[u][0], qfl[u][1], qfl[u][2], qfl[u][3], bh0, bh1);
                }
        }

        // ---- mask ----
#pragma unroll
        for (int nt = 0; nt < 4; nt++) {
            int kb0 = wh * 32 + nt * 8 + tig * 2;
            int m0v = msk[kb0], m1v = msk[kb0 + 1];
#pragma unroll
            for (int c = 0; c < 4; c++) {
                if (!m0v) { sc[c][nt][0] = -1e9f; sc[c][nt][2] = -1e9f; }
                if (!m1v) { sc[c][nt][1] = -1e9f; sc[c][nt][3] = -1e9f; }
            }
        }

        // ---- online softmax (cross warp-pair via stats smem) ----
        float rmx[4][2];
#pragma unroll
        for (int c = 0; c < 4; c++) {
            float r0 = -1e30f, r1 = -1e30f;
#pragma unroll
            for (int nt = 0; nt < 4; nt++) {
                r0 = fmaxf(r0, fmaxf(sc[c][nt][0], sc[c][nt][1]));
                r1 = fmaxf(r1, fmaxf(sc[c][nt][2], sc[c][nt][3]));
            }
            r0 = fmaxf(r0, __shfl_xor_sync(0xffffffffu, r0, 1));
            r0 = fmaxf(r0, __shfl_xor_sync(0xffffffffu, r0, 2));
            r1 = fmaxf(r1, __shfl_xor_sync(0xffffffffu, r1, 1));
            r1 = fmaxf(r1, __shfl_xor_sync(0xffffffffu, r1, 2));
            rmx[c][0] = r0; rmx[c][1] = r1;
            if (tig == 0) {
                stats[(c * 64 + m16 + gid) * 2 + wh] = r0;
                stats[(c * 64 + m16 + gid + 8) * 2 + wh] = r1;
            }
        }
        __syncthreads();

        float corr[4][2], ssum[4][2];
#pragma unroll
        for (int c = 0; c < 4; c++) {
            float o0 = stats[(c * 64 + m16 + gid) * 2 + (wh ^ 1)];
            float o1 = stats[(c * 64 + m16 + gid + 8) * 2 + (wh ^ 1)];
            float mn0 = fmaxf(mrun[c][0], fmaxf(rmx[c][0], o0));
            float mn1 = fmaxf(mrun[c][1], fmaxf(rmx[c][1], o1));
            corr[c][0] = __expf(mrun[c][0] - mn0);
            corr[c][1] = __expf(mrun[c][1] - mn1);
            mrun[c][0] = mn0; mrun[c][1] = mn1;
            float s0 = 0.f, s1 = 0.f;
#pragma unroll
            for (int nt = 0; nt < 4; nt++) {
                sc[c][nt][0] = __expf(sc[c][nt][0] - mn0);
                sc[c][nt][1] = __expf(sc[c][nt][1] - mn0);
                sc[c][nt][2] = __expf(sc[c][nt][2] - mn1);
                sc[c][nt][3] = __expf(sc[c][nt][3] - mn1);
                s0 += sc[c][nt][0] + sc[c][nt][1];
                s1 += sc[c][nt][2] + sc[c][nt][3];
            }
            s0 += __shfl_xor_sync(0xffffffffu, s0, 1);
            s0 += __shfl_xor_sync(0xffffffffu, s0, 2);
            s1 += __shfl_xor_sync(0xffffffffu, s1, 1);
            s1 += __shfl_xor_sync(0xffffffffu, s1, 2);
            ssum[c][0] = s0; ssum[c][1] = s1;
        }
        __syncthreads();   // max reads done before overwriting stats
#pragma unroll
        for (int c = 0; c < 4; c++)
            if (tig == 0) {
                stats[(c * 64 + m16 + gid) * 2 + wh] = ssum[c][0];
                stats[(c * 64 + m16 + gid + 8) * 2 + wh] = ssum[c][1];
            }
        __syncthreads();
#pragma unroll
        for (int c = 0; c < 4; c++) {
            float o0 = stats[(c * 64 + m16 + gid) * 2 + (wh ^ 1)];
            float o1 = stats[(c * 64 + m16 + gid + 8) * 2 + (wh ^ 1)];
            lrun[c][0] = lrun[c][0] * corr[c][0] + ssum[c][0] + o0;
            lrun[c][1] = lrun[c][1] * corr[c][1] + ssum[c][1] + o1;
#pragma unroll
            for (int nt = 0; nt < 4; nt++) {
                U[c][nt][0] *= corr[c][0];
                U[c][nt][1] *= corr[c][0];
                U[c][nt][2] *= corr[c][1];
                U[c][nt][3] *= corr[c][1];
            }
            // pack P -> bf16 hi/lo in smem [c][row][key]
#pragma unroll
            for (int nt = 0; nt < 4; nt++) {
                int key = wh * 32 + nt * 8 + tig * 2;
                u32 h01, l01;
                BFPACK(h01, sc[c][nt][0], sc[c][nt][1]);
                float rx = sc[c][nt][0] - __uint_as_float(h01 << 16);
                float ry = sc[c][nt][1] - __uint_as_float(h01 & 0xffff0000u);
                BFPACK(l01, rx, ry);
                int ro = (c * 64 + m16 + gid) * STR + key;
                *(u32*)(sm + S_PH + ro) = h01;
                *(u32*)(sm + S_PL + ro) = l01;
                BFPACK(h01, sc[c][nt][2], sc[c][nt][3]);
                rx = sc[c][nt][2] - __uint_as_float(h01 << 16);
                ry = sc[c][nt][3] - __uint_as_float(h01 & 0xffff0000u);
                BFPACK(l01, rx, ry);
                ro = (c * 64 + m16 + gid + 8) * STR + key;
                *(u32*)(sm + S_PH + ro) = h01;
                *(u32*)(sm + S_PL + ro) = l01;
            }
        }
        __syncthreads();

        // ---- PV MMAs: U_c[16 x 32(out half)] += P_c @ (sign/perm V) ----
        // A-frags cover all 64 keys; out cols split by wh -> partials complete.
#pragma unroll
        for (int c = 0; c < 4; c++) {
#pragma unroll
            for (int u = 0; u < 4; u++) {
                int ao = (c * 64 + m16 + gid) * STR + u * 16 + tig * 2;
                u32 pa0 = *(const u32*)(sm + S_PH + ao);
                u32 pa1 = *(const u32*)(sm + S_PH + ao + 8 * STR);
                u32 pa2 = *(const u32*)(sm + S_PH + ao + 8);
                u32 pa3 = *(const u32*)(sm + S_PH + ao + 8 * STR + 8);
                u32 la0 = *(const u32*)(sm + S_PL + ao);
                u32 la1 = *(const u32*)(sm + S_PL + ao + 8 * STR);
                u32 la2 = *(const u32*)(sm + S_PL + ao + 8);
                u32 la3 = *(const u32*)(sm + S_PL + ao + 8 * STR + 8);
#pragma unroll
                for (int nt = 0; nt < 4; nt++) {
                    int oc = wh * 2 + (nt >> 1);
                    int src = tsrc[c][oc];
                    u32 smask = (tsgn[c][oc] < 0) ? SGNM : 0u;
                    int bo = (src * 16 + (nt & 1) * 8 + gid) * STR + u * 16 + tig * 2;
                    u32 vh0 = *(const u32*)(sm + S_VH + bo) ^ smask;
                    u32 vh1 = *(const u32*)(sm + S_VH + bo + 8) ^ smask;
                    u32 vl0 = *(const u32*)(sm + S_VL + bo) ^ smask;
                    u32 vl1 = *(const u32*)(sm + S_VL + bo + 8) ^ smask;
                    HMMA(U[c][nt], pa0, pa1, pa2, pa3, vh0, vh1);
                    HMMA(U[c][nt], pa0, pa1, pa2, pa3, vl0, vl1);
                    HMMA(U[c][nt], la0, la1, la2, la3, vh0, vh1);
                }
            }
        }
    }

    // ---- epilogue: normalize into smem, SUM over channels (sign/perm already
    // applied in the PV MMAs), write ----
    __syncthreads();
    float* Uc = (float*)(sm + S_PH);   // [4][64][68], aliases P region
#pragma unroll
    for (int c = 0; c < 4; c++) {
        float inv0 = 1.f / lrun[c][0];
        float inv1 = 1.f / lrun[c][1];
#pragma unroll
        for (int nt = 0; nt < 4; nt++) {
            int col = wh * 32 + nt * 8 + tig * 2;
            *(float2*)&Uc[(c * 64 + m16 + gid) * 68 + col] =
                make_float2(U[c][nt][0] * inv0, U[c][nt][1] * inv0);
            *(float2*)&Uc[(c * 64 + m16 + gid + 8) * 68 + col] =
                make_float2(U[c][nt][2] * inv1, U[c][nt][3] * inv1);
        }
    }
    __syncthreads();

    float* Og = g_O + (size_t)(b * SQ) * DM + h * DKH;
#pragma unroll
    for (int i = 0; i < 16; i++) {
        int idx = i * 256 + tid;
        int q = idx >> 6, col = idx & 63;
        float o = 0.f;
#pragma unroll
        for (int ch = 0; ch < 4; ch++)
            o += Uc[(ch * 64 + q) * 68 + col];
        Og[(size_t)(q0 + q) * DM + col] = o;
    }
}

// ---------------------------------------------------------------------------
extern "C" void kernel_launch(void* const* d_in, const int* in_sizes, int n_in,
                              void* d_out, int out_size)
{
    (void)in_sizes; (void)n_in; (void)out_size;
    // 0 q, 1 k, 2 v, 3 mask, 4-19 weights, 20 bq, 21 bk, 22 bv, 23 bo
    WPtrs wp;
    for (int i = 0; i < 16; i++) wp.w[i] = (const float*)d_in[4 + i];

    build_wbig_kernel<<<dim3(32, 32, 4), 256>>>(wp);

    GemmArgs ga;
    for (int z = 0; z < 3; z++) {
        ga.A[z]    = (const float*)d_in[z];
        ga.bias[z] = (const float*)d_in[20 + z];
    }
    dim3 qkvgrid(DM / 128, MROWS / 128, 3);
    qkv_gemm_kernel<<<qkvgrid, 256>>>(ga);

    cudaFuncSetAttribute(quat_attn_tc_kernel,
                         cudaFuncAttributeMaxDynamicSharedMemorySize, ATT_SMEM_BYTES);
    quat_attn_tc_kernel<<<dim3(SQ / 64, BSZ * NH), 256, ATT_SMEM_BYTES>>>(
        (const int*)d_in[3]);

    dim3 ogrid(DM / 128, MROWS / 128);
    o_gemm_kernel<<<ogrid, 256>>>((const float*)d_in[23], (float*)d_out);
}

// round 9
// speedup vs baseline: 2.2805x; 1.1217x over previous
#include <cuda_runtime.h>
#include <cuda_bf16.h>
#include <cstdint>
#include <math.h>

#define SQ   1024
#define DM   1024
#define NH   16
#define DKH  64
#define BSZ  2
#define MROWS (BSZ*SQ)

typedef uint32_t u32;

// ---------------------------------------------------------------------------
// Device scratch
// ---------------------------------------------------------------------------
__device__ __nv_bfloat16 g_Wth[4][DM*DM];  // W^T hi (K-major [n][k])
__device__ __nv_bfloat16 g_Wtl[4][DM*DM];  // W^T lo
__device__ float g_P[2][MROWS*DM];         // projected Q,K
__device__ float g_Vt[BSZ*NH*DKH*SQ];      // projected V, transposed [b,h,d,S]
__device__ float g_O[MROWS*DM];            // attention output

__constant__ int   c_SRC[16] = {0,1,2,3,  1,0,3,2,  2,3,0,1,  3,2,1,0};
__constant__ float c_SGN[16] = {1.f,1.f,1.f,1.f,  -1.f,1.f,-1.f,1.f,
                                -1.f,1.f,1.f,-1.f, -1.f,-1.f,1.f,1.f};

struct WPtrs { const float* w[16]; };
struct GemmArgs { const float* A[3]; const float* bias[3]; };

#define BFPACK(r, flo, fhi) \
    asm("cvt.rn.bf16x2.f32 %0, %1, %2;" : "=r"(r) : "f"(fhi), "f"(flo))

#define HMMA(c, a0, a1, a2, a3, b0, b1) \
    asm volatile("mma.sync.aligned.m16n8k16.row.col.f32.bf16.bf16.f32 " \
        "{%0,%1,%2,%3}, {%4,%5,%6,%7}, {%8,%9}, {%0,%1,%2,%3};" \
        : "+f"((c)[0]), "+f"((c)[1]), "+f"((c)[2]), "+f"((c)[3]) \
        : "r"(a0), "r"(a1), "r"(a2), "r"(a3), "r"(b0), "r"(b1))

#define SGNM 0x80008000u

// ---------------------------------------------------------------------------
__global__ __launch_bounds__(256)
void build_wbig_kernel(WPtrs p) {
    __shared__ float s[32][33];
    int tx = threadIdx.x & 31, ty = threadIdx.x >> 5;
    int k0 = blockIdx.x * 32, n0 = blockIdx.y * 32, which = blockIdx.z;
    int rb = k0 >> 8, cb = n0 >> 8;
    float sgn = c_SGN[rb * 4 + cb];
    const float* src = p.w[which * 4 + c_SRC[rb * 4 + cb]];
#pragma unroll
    for (int i = 0; i < 4; i++) {
        int kl = ty + i * 8;
        s[kl][tx] = sgn * src[((k0 + kl) & 255) * 256 + ((n0 + tx) & 255)];
    }
    __syncthreads();
#pragma unroll
    for (int i = 0; i < 4; i++) {
        int nl = ty + i * 8;
        float v = s[tx][nl];
        __nv_bfloat16 hi = __float2bfloat16_rn(v);
        __nv_bfloat16 lo = __float2bfloat16_rn(v - __bfloat162float(hi));
        size_t o = (size_t)(n0 + nl) * DM + k0 + tx;
        g_Wth[which][o] = hi;
        g_Wtl[which][o] = lo;
    }
}

// ---------------------------------------------------------------------------
// Tensor-core GEMM, double-buffered. vt!=0: write V output transposed to g_Vt.
// Dynamic smem: 2 stages x {Ah, Al, Wh, Wl} of 128xKCP bf16.
// ---------------------------------------------------------------------------
#define KCP 40
#define GST (128 * KCP)                    // elements per tile array
#define GEMM_SMEM_BYTES (2 * 4 * GST * 2)  // 81920 B

__device__ __forceinline__
void gemm_store_stage(__nv_bfloat16* base, int tid,
                      const float4 aR[4], const uint4 whR[2], const uint4 wlR[2])
{
    __nv_bfloat16* Ah_s = base;
    __nv_bfloat16* Al_s = base + GST;
    __nv_bfloat16* Wh_s = base + 2 * GST;
    __nv_bfloat16* Wl_s = base + 3 * GST;
#pragma unroll
    for (int i = 0; i < 4; i++) {
        int idx = tid + i * 256;
        int r = idx >> 3, c4 = (idx & 7) * 4;
        float4 a = aR[i];
        u32 h01, h23, l01, l23;
        BFPACK(h01, a.x, a.y);
        BFPACK(h23, a.z, a.w);
        float rx = a.x - __uint_as_float(h01 << 16);
        float ry = a.y - __uint_as_float(h01 & 0xffff0000u);
        float rz = a.z - __uint_as_float(h23 << 16);
        float rw = a.w - __uint_as_float(h23 & 0xffff0000u);
        BFPACK(l01, rx, ry);
        BFPACK(l23, rz, rw);
        int so = r * KCP + c4;
        *(uint2*)(Ah_s + so) = make_uint2(h01, h23);
        *(uint2*)(Al_s + so) = make_uint2(l01, l23);
    }
#pragma unroll
    for (int i = 0; i < 2; i++) {
        int idx = tid + i * 256;
        int r = idx >> 2, c8 = (idx & 3) * 8;
        int so = r * KCP + c8;
        *(uint4*)(Wh_s + so) = whR[i];
        *(uint4*)(Wl_s + so) = wlR[i];
    }
}

__device__ __forceinline__
void tc_gemm_body(__nv_bfloat16* gsm, const float* __restrict__ A,
                  const __nv_bfloat16* __restrict__ Wh,
                  const __nv_bfloat16* __restrict__ Wl,
                  const float* __restrict__ bias, float* __restrict__ C, int vt)
{
    int tid = threadIdx.x;
    int wid = tid >> 5, lane = tid & 31;
    int gid = lane >> 2, tig = lane & 3;
    int wm = wid & 1, wn = wid >> 1;
    int m0 = blockIdx.y * 128, n0 = blockIdx.x * 128;

    float acc[4][4][4];
#pragma unroll
    for (int mi = 0; mi < 4; mi++)
#pragma unroll
        for (int ni = 0; ni < 4; ni++)
#pragma unroll
            for (int j = 0; j < 4; j++) acc[mi][ni][j] = 0.f;

    float4 aR[4]; uint4 whR[2], wlR[2];
    // preload tile 0
    {
        const float* Ar = A + (size_t)m0 * DM;
#pragma unroll
        for (int i = 0; i < 4; i++) {
            int idx = tid + i * 256;
            int r = idx >> 3, c4 = (idx & 7) * 4;
            aR[i] = *(const float4*)(Ar + (size_t)r * DM + c4);
        }
#pragma unroll
        for (int i = 0; i < 2; i++) {
            int idx = tid + i * 256;
            int r = idx >> 2, c8 = (idx & 3) * 8;
            size_t go = (size_t)(n0 + r) * DM + c8;
            whR[i] = *(const uint4*)(Wh + go);
            wlR[i] = *(const uint4*)(Wl + go);
        }
    }
    gemm_store_stage(gsm, tid, aR, whR, wlR);
    __syncthreads();

    for (int kt = 0; kt < 32; kt++) {
        // prefetch next tile into registers (overlaps with MMA phase)
        if (kt < 31) {
            int k0n = (kt + 1) * 32;
            const float* Ar = A + (size_t)m0 * DM + k0n;
#pragma unroll
            for (int i = 0; i < 4; i++) {
                int idx = tid + i * 256;
                int r = idx >> 3, c4 = (idx & 7) * 4;
                aR[i] = *(const float4*)(Ar + (size_t)r * DM + c4);
            }
#pragma unroll
            for (int i = 0; i < 2; i++) {
                int idx = tid + i * 256;
                int r = idx >> 2, c8 = (idx & 3) * 8;
                size_t go = (size_t)(n0 + r) * DM + k0n + c8;
                whR[i] = *(const uint4*)(Wh + go);
                wlR[i] = *(const uint4*)(Wl + go);
            }
        }

        __nv_bfloat16* st = gsm + (size_t)(kt & 1) * 4 * GST;
        __nv_bfloat16* Ah_s = st;
        __nv_bfloat16* Al_s = st + GST;
        __nv_bfloat16* Wh_s = st + 2 * GST;
        __nv_bfloat16* Wl_s = st + 3 * GST;

#pragma unroll
        for (int ks = 0; ks < 2; ks++) {
            int kb = ks * 16 + tig * 2;
            u32 bh[4][2], bl[4][2];
#pragma unroll
            for (int ni = 0; ni < 4; ni++) {
                int n = wn * 32 + ni * 8 + gid;
                int off = n * KCP + kb;
                bh[ni][0] = *(const u32*)(Wh_s + off);
                bh[ni][1] = *(const u32*)(Wh_s + off + 8);
                bl[ni][0] = *(const u32*)(Wl_s + off);
                bl[ni][1] = *(const u32*)(Wl_s + off + 8);
            }
#pragma unroll
            for (int mi = 0; mi < 4; mi++) {
                int r = wm * 64 + mi * 16 + gid;
                int off = r * KCP + kb;
                u32 ah0 = *(const u32*)(Ah_s + off);
                u32 ah1 = *(const u32*)(Ah_s + off + 8 * KCP);
                u32 ah2 = *(const u32*)(Ah_s + off + 8);
                u32 ah3 = *(const u32*)(Ah_s + off + 8 * KCP + 8);
                u32 al0 = *(const u32*)(Al_s + off);
                u32 al1 = *(const u32*)(Al_s + off + 8 * KCP);
                u32 al2 = *(const u32*)(Al_s + off + 8);
                u32 al3 = *(const u32*)(Al_s + off + 8 * KCP + 8);
#pragma unroll
                for (int ni = 0; ni < 4; ni++) {
                    HMMA(acc[mi][ni], ah0, ah1, ah2, ah3, bh[ni][0], bh[ni][1]);
                    HMMA(acc[mi][ni], ah0, ah1, ah2, ah3, bl[ni][0], bl[ni][1]);
                    HMMA(acc[mi][ni], al0, al1, al2, al3, bh[ni][0], bh[ni][1]);
                }
            }
        }
        if (kt < 31)
            gemm_store_stage(gsm + (size_t)((kt + 1) & 1) * 4 * GST, tid, aR, whR, wlR);
        __syncthreads();
    }

#pragma unroll
    for (int mi = 0; mi < 4; mi++) {
        int r = m0 + wm * 64 + mi * 16 + gid;
#pragma unroll
        for (int ni = 0; ni < 4; ni++) {
            int c = n0 + wn * 32 + ni * 8 + tig * 2;
            float b0 = bias[c], b1 = bias[c + 1];
            if (!vt) {
                *(float2*)(C + (size_t)r * DM + c) =
                    make_float2(acc[mi][ni][0] + b0, acc[mi][ni][1] + b1);
                *(float2*)(C + (size_t)(r + 8) * DM + c) =
                    make_float2(acc[mi][ni][2] + b0, acc[mi][ni][3] + b1);
            } else {
                int b = r >> 10, s = r & 1023;
                int h = c >> 6, d = c & 63;
                float* base = g_Vt + ((size_t)(b * NH + h) * DKH) * SQ;
                base[(size_t)d * SQ + s]           = acc[mi][ni][0] + b0;
                base[(size_t)(d + 1) * SQ + s]     = acc[mi][ni][1] + b1;
                base[(size_t)d * SQ + s + 8]       = acc[mi][ni][2] + b0;
                base[(size_t)(d + 1) * SQ + s + 8] = acc[mi][ni][3] + b1;
            }
        }
    }
}

__global__ __launch_bounds__(256)
void qkv_gemm_kernel(GemmArgs args) {
    extern __shared__ __nv_bfloat16 gsm[];
    int z = blockIdx.z;
    tc_gemm_body(gsm, args.A[z], g_Wth[z], g_Wtl[z], args.bias[z],
                 z < 2 ? g_P[z] : nullptr, z == 2);
}
__global__ __launch_bounds__(256)
void o_gemm_kernel(const float* __restrict__ bias, float* __restrict__ Cout) {
    extern __shared__ __nv_bfloat16 gsm[];
    tc_gemm_body(gsm, g_O, g_Wth[3], g_Wtl[3], bias, Cout, 0);
}

// ---------------------------------------------------------------------------
// Tensor-core quaternion flash attention.
// Block 256 thr = 8 warps: warp = (mtile 0..3 [16 q rows], wh 0..1 [key/out half]).
// Single-exchange flash softmax merge; register epilogue (channels in-warp).
// ---------------------------------------------------------------------------
#define STR 72            // bf16 tile row stride (elements)
#define TILE_B (64*STR)   // elements per 64-row tile

#define S_QH  0
#define S_QL  (S_QH + TILE_B)
#define S_KH  (S_QL + TILE_B)
#define S_KL  (S_KH + TILE_B)
#define S_VH  (S_KL + TILE_B)
#define S_VL  (S_VH + TILE_B)
#define S_PH  (S_VL + TILE_B)           // [4][64][STR]
#define S_PL  (S_PH + 4*TILE_B)
#define S_END (S_PL + 4*TILE_B)
#define ATT_SMEM_BYTES (S_END*2 + 4*64*2*8 + 256)

__global__ __launch_bounds__(256, 1)
void quat_attn_tc_kernel(const int* __restrict__ mask)
{
    extern __shared__ __nv_bfloat16 sm[];
    float2* stats2 = (float2*)(sm + S_END);     // [4][64][2] (max, expsum)
    int*    msk    = (int*)(stats2 + 4 * 64 * 2);

    const int tsrc[4][4] = {{0,1,2,3},{1,0,3,2},{2,3,0,1},{3,2,1,0}};
    const int tsgn[4][4] = {{1,1,1,1},{-1,1,-1,1},{-1,1,1,-1},{-1,-1,1,1}};

    int tid = threadIdx.x;
    int wid = tid >> 5, lane = tid & 31;
    int gid = lane >> 2, tig = lane & 3;
    int mtile = wid >> 1, wh = wid & 1;
    int m16 = mtile * 16;
    int bh = blockIdx.y;
    int b = bh >> 4, h = bh & 15;
    int q0 = blockIdx.x * 64;

    const float* Qg = g_P[0] + (size_t)(b * SQ) * DM + h * DKH;
    const float* Kg = g_P[1] + (size_t)(b * SQ) * DM + h * DKH;
    const float* Vg = g_Vt + (size_t)bh * DKH * SQ;
    const int*   mrow = mask + b * SQ;

    // ---- load Q tile (scaled by 1/8), bf16 hi/lo split ----
#pragma unroll
    for (int i = 0; i < 4; i++) {
        int idx = tid + i * 256;
        int r = idx >> 4, c4 = (idx & 15) * 4;
        float4 a = *(const float4*)(Qg + (size_t)(q0 + r) * DM + c4);
        a.x *= 0.125f; a.y *= 0.125f; a.z *= 0.125f; a.w *= 0.125f;
        u32 h01, h23, l01, l23;
        BFPACK(h01, a.x, a.y);
        BFPACK(h23, a.z, a.w);
        float rx = a.x - __uint_as_float(h01 << 16);
        float ry = a.y - __uint_as_float(h01 & 0xffff0000u);
        float rz = a.z - __uint_as_float(h23 << 16);
        float rw = a.w - __uint_as_float(h23 & 0xffff0000u);
        BFPACK(l01, rx, ry);
        BFPACK(l23, rz, rw);
        *(uint2*)(sm + S_QH + r * STR + c4) = make_uint2(h01, h23);
        *(uint2*)(sm + S_QL + r * STR + c4) = make_uint2(l01, l23);
    }
    __syncthreads();

    // ---- persistent Q fragments ----
    u32 qfh[4][4], qfl[4][4];
#pragma unroll
    for (int u = 0; u < 4; u++) {
        int off = (m16 + gid) * STR + u * 16 + tig * 2;
        qfh[u][0] = *(const u32*)(sm + S_QH + off);
        qfh[u][1] = *(const u32*)(sm + S_QH + off + 8 * STR);
        qfh[u][2] = *(const u32*)(sm + S_QH + off + 8);
        qfh[u][3] = *(const u32*)(sm + S_QH + off + 8 * STR + 8);
        qfl[u][0] = *(const u32*)(sm + S_QL + off);
        qfl[u][1] = *(const u32*)(sm + S_QL + off + 8 * STR);
        qfl[u][2] = *(const u32*)(sm + S_QL + off + 8);
        qfl[u][3] = *(const u32*)(sm + S_QL + off + 8 * STR + 8);
    }

    float mrun[4][2], lrun[4][2];
    float U[4][4][4];
#pragma unroll
    for (int c = 0; c < 4; c++) {
#pragma unroll
        for (int j = 0; j < 2; j++) { mrun[c][j] = -1e30f; lrun[c][j] = 0.f; }
#pragma unroll
        for (int nt = 0; nt < 4; nt++)
#pragma unroll
            for (int j = 0; j < 4; j++) U[c][nt][j] = 0.f;
    }

    for (int n0 = 0; n0 < SQ; n0 += 64) {
        __syncthreads();
        // ---- load K tile and Vt tile, hi/lo split ----
#pragma unroll
        for (int i = 0; i < 4; i++) {
            int idx = tid + i * 256;
            int r = idx >> 4, c4 = (idx & 15) * 4;
            float4 a = *(const float4*)(Kg + (size_t)(n0 + r) * DM + c4);
            u32 h01, h23, l01, l23;
            BFPACK(h01, a.x, a.y);
            BFPACK(h23, a.z, a.w);
            float rx = a.x - __uint_as_float(h01 << 16);
            float ry = a.y - __uint_as_float(h01 & 0xffff0000u);
            float rz = a.z - __uint_as_float(h23 << 16);
            float rw = a.w - __uint_as_float(h23 & 0xffff0000u);
            BFPACK(l01, rx, ry);
            BFPACK(l23, rz, rw);
            *(uint2*)(sm + S_KH + r * STR + c4) = make_uint2(h01, h23);
            *(uint2*)(sm + S_KL + r * STR + c4) = make_uint2(l01, l23);

            float4 v = *(const float4*)(Vg + (size_t)r * SQ + n0 + c4);
            BFPACK(h01, v.x, v.y);
            BFPACK(h23, v.z, v.w);
            rx = v.x - __uint_as_float(h01 << 16);
            ry = v.y - __uint_as_float(h01 & 0xffff0000u);
            rz = v.z - __uint_as_float(h23 << 16);
            rw = v.w - __uint_as_float(h23 & 0xffff0000u);
            BFPACK(l01, rx, ry);
            BFPACK(l23, rz, rw);
            *(uint2*)(sm + S_VH + r * STR + c4) = make_uint2(h01, h23);
            *(uint2*)(sm + S_VL + r * STR + c4) = make_uint2(l01, l23);
        }
        if (tid < 64) msk[tid] = mrow[n0 + tid];
        __syncthreads();

        // ---- score MMAs ----
        float sc[4][4][4];
#pragma unroll
        for (int c = 0; c < 4; c++)
#pragma unroll
            for (int nt = 0; nt < 4; nt++)
#pragma unroll
                for (int j = 0; j < 4; j++) sc[c][nt][j] = 0.f;

#pragma unroll
        for (int nt = 0; nt < 4; nt++) {
            int kb0 = wh * 32 + nt * 8;
            u32 kf[4][2][2];
#pragma unroll
            for (int comp = 0; comp < 4; comp++) {
                int off = (kb0 + gid) * STR + comp * 16 + tig * 2;
                kf[comp][0][0] = *(const u32*)(sm + S_KH + off);
                kf[comp][0][1] = *(const u32*)(sm + S_KH + off + 8);
                kf[comp][1][0] = *(const u32*)(sm + S_KL + off);
                kf[comp][1][1] = *(const u32*)(sm + S_KL + off + 8);
            }
#pragma unroll
            for (int c = 0; c < 4; c++)
#pragma unroll
                for (int u = 0; u < 4; u++) {
                    int src = tsrc[u][c];
                    u32 bh0 = kf[src][0][0], bh1 = kf[src][0][1];
                    u32 bl0 = kf[src][1][0], bl1 = kf[src][1][1];
                    if (tsgn[u][c] < 0) {
                        bh0 ^= SGNM; bh1 ^= SGNM; bl0 ^= SGNM; bl1 ^= SGNM;
                    }
                    HMMA(sc[c][nt], qfh[u][0], qfh[u][1], qfh[u][2], qfh[u][3], bh0, bh1);
                    HMMA(sc[c][nt], qfh[u][0], qfh[u][1], qfh[u][2], qfh[u][3], bl0, bl1);
                    HMMA(sc[c][nt], qfl[u][0], qfl[u][1], qfl[u][2], qfl[u][3], bh0, bh1);
                }
        }

        // ---- mask ----
#pragma unroll
        for (int nt = 0; nt < 4; nt++) {
            int kb0 = wh * 32 + nt * 8 + tig * 2;
            int m0v = msk[kb0], m1v = msk[kb0 + 1];
#pragma unroll
            for (int c = 0; c < 4; c++) {
                if (!m0v) { sc[c][nt][0] = -1e9f; sc[c][nt][2] = -1e9f; }
                if (!m1v) { sc[c][nt][1] = -1e9f; sc[c][nt][3] = -1e9f; }
            }
        }

        // ---- per-warp tile softmax (local max + expsum), single exchange ----
        float tmx[4][2], tsum[4][2];
#pragma unroll
        for (int c = 0; c < 4; c++) {
            float t0 = -1e30f, t1 = -1e30f;
#pragma unroll
            for (int nt = 0; nt < 4; nt++) {
                t0 = fmaxf(t0, fmaxf(sc[c][nt][0], sc[c][nt][1]));
                t1 = fmaxf(t1, fmaxf(sc[c][nt][2], sc[c][nt][3]));
            }
            t0 = fmaxf(t0, __shfl_xor_sync(0xffffffffu, t0, 1));
            t0 = fmaxf(t0, __shfl_xor_sync(0xffffffffu, t0, 2));
            t1 = fmaxf(t1, __shfl_xor_sync(0xffffffffu, t1, 1));
            t1 = fmaxf(t1, __shfl_xor_sync(0xffffffffu, t1, 2));
            float s0 = 0.f, s1 = 0.f;
#pragma unroll
            for (int nt = 0; nt < 4; nt++) {
                sc[c][nt][0] = __expf(sc[c][nt][0] - t0);
                sc[c][nt][1] = __expf(sc[c][nt][1] - t0);
                sc[c][nt][2] = __expf(sc[c][nt][2] - t1);
                sc[c][nt][3] = __expf(sc[c][nt][3] - t1);
                s0 += sc[c][nt][0] + sc[c][nt][1];
                s1 += sc[c][nt][2] + sc[c][nt][3];
            }
            s0 += __shfl_xor_sync(0xffffffffu, s0, 1);
            s0 += __shfl_xor_sync(0xffffffffu, s0, 2);
            s1 += __shfl_xor_sync(0xffffffffu, s1, 1);
            s1 += __shfl_xor_sync(0xffffffffu, s1, 2);
            tmx[c][0] = t0; tmx[c][1] = t1;
            tsum[c][0] = s0; tsum[c][1] = s1;
            if (tig == 0) {
                stats2[(c * 64 + m16 + gid) * 2 + wh] = make_float2(t0, s0);
                stats2[(c * 64 + m16 + gid + 8) * 2 + wh] = make_float2(t1, s1);
            }
        }
        __syncthreads();

        // ---- merge with partner half, rescale U, pack scaled P ----
#pragma unroll
        for (int c = 0; c < 4; c++) {
            float2 o0 = stats2[(c * 64 + m16 + gid) * 2 + (wh ^ 1)];
            float2 o1 = stats2[(c * 64 + m16 + gid + 8) * 2 + (wh ^ 1)];
            float mn0 = fmaxf(mrun[c][0], fmaxf(tmx[c][0], o0.x));
            float mn1 = fmaxf(mrun[c][1], fmaxf(tmx[c][1], o1.x));
            float corr0 = __expf(mrun[c][0] - mn0);
            float corr1 = __expf(mrun[c][1] - mn1);
            float f0 = __expf(tmx[c][0] - mn0);
            float f1 = __expf(tmx[c][1] - mn1);
            float g0 = __expf(o0.x - mn0);
            float g1 = __expf(o1.x - mn1);
            lrun[c][0] = lrun[c][0] * corr0 + tsum[c][0] * f0 + o0.y * g0;
            lrun[c][1] = lrun[c][1] * corr1 + tsum[c][1] * f1 + o1.y * g1;
            mrun[c][0] = mn0; mrun[c][1] = mn1;
#pragma unroll
            for (int nt = 0; nt < 4; nt++) {
                U[c][nt][0] *= corr0;
                U[c][nt][1] *= corr0;
                U[c][nt][2] *= corr1;
                U[c][nt][3] *= corr1;
            }
#pragma unroll
            for (int nt = 0; nt < 4; nt++) {
                int key = wh * 32 + nt * 8 + tig * 2;
                float p0 = sc[c][nt][0] * f0, p1 = sc[c][nt][1] * f0;
                u32 h01, l01;
                BFPACK(h01, p0, p1);
                float rx = p0 - __uint_as_float(h01 << 16);
                float ry = p1 - __uint_as_float(h01 & 0xffff0000u);
                BFPACK(l01, rx, ry);
                int ro = (c * 64 + m16 + gid) * STR + key;
                *(u32*)(sm + S_PH + ro) = h01;
                *(u32*)(sm + S_PL + ro) = l01;
                float p2 = sc[c][nt][2] * f1, p3 = sc[c][nt][3] * f1;
                BFPACK(h01, p2, p3);
                rx = p2 - __uint_as_float(h01 << 16);
                ry = p3 - __uint_as_float(h01 & 0xffff0000u);
                BFPACK(l01, rx, ry);
                ro = (c * 64 + m16 + gid + 8) * STR + key;
                *(u32*)(sm + S_PH + ro) = h01;
                *(u32*)(sm + S_PL + ro) = l01;
            }
        }
        __syncthreads();

        // ---- PV MMAs: U_c[16 x 32(out half)] += P_c @ (sign/perm V) ----
#pragma unroll
        for (int c = 0; c < 4; c++) {
#pragma unroll
            for (int u = 0; u < 4; u++) {
                int ao = (c * 64 + m16 + gid) * STR + u * 16 + tig * 2;
                u32 pa0 = *(const u32*)(sm + S_PH + ao);
                u32 pa1 = *(const u32*)(sm + S_PH + ao + 8 * STR);
                u32 pa2 = *(const u32*)(sm + S_PH + ao + 8);
                u32 pa3 = *(const u32*)(sm + S_PH + ao + 8 * STR + 8);
                u32 la0 = *(const u32*)(sm + S_PL + ao);
                u32 la1 = *(const u32*)(sm + S_PL + ao + 8 * STR);
                u32 la2 = *(const u32*)(sm + S_PL + ao + 8);
                u32 la3 = *(const u32*)(sm + S_PL + ao + 8 * STR + 8);
#pragma unroll
                for (int nt = 0; nt < 4; nt++) {
                    int oc = wh * 2 + (nt >> 1);
                    int src = tsrc[c][oc];
                    u32 smask = (tsgn[c][oc] < 0) ? SGNM : 0u;
                    int bo = (src * 16 + (nt & 1) * 8 + gid) * STR + u * 16 + tig * 2;
                    u32 vh0 = *(const u32*)(sm + S_VH + bo) ^ smask;
                    u32 vh1 = *(const u32*)(sm + S_VH + bo + 8) ^ smask;
                    u32 vl0 = *(const u32*)(sm + S_VL + bo) ^ smask;
                    u32 vl1 = *(const u32*)(sm + S_VL + bo + 8) ^ smask;
                    HMMA(U[c][nt], pa0, pa1, pa2, pa3, vh0, vh1);
                    HMMA(U[c][nt], pa0, pa1, pa2, pa3, vl0, vl1);
                    HMMA(U[c][nt], la0, la1, la2, la3, vh0, vh1);
                }
            }
        }
    }

    // ---- register epilogue: all 4 channels in-warp; sum normalized partials ----
    float inv[4][2];
#pragma unroll
    for (int c = 0; c < 4; c++) {
        inv[c][0] = 1.f / lrun[c][0];
        inv[c][1] = 1.f / lrun[c][1];
    }
    float* Og = g_O + (size_t)(b * SQ) * DM + h * DKH;
    int r0 = q0 + m16 + gid;
#pragma unroll
    for (int nt = 0; nt < 4; nt++) {
        int col = wh * 32 + nt * 8 + tig * 2;
        float o0 = 0.f, o1 = 0.f, o2 = 0.f, o3 = 0.f;
#pragma unroll
        for (int c = 0; c < 4; c++) {
            o0 += U[c][nt][0] * inv[c][0];
            o1 += U[c][nt][1] * inv[c][0];
            o2 += U[c][nt][2] * inv[c][1];
            o3 += U[c][nt][3] * inv[c][1];
        }
        *(float2*)(Og + (size_t)r0 * DM + col) = make_float2(o0, o1);
        *(float2*)(Og + (size_t)(r0 + 8) * DM + col) = make_float2(o2, o3);
    }
}

// ---------------------------------------------------------------------------
extern "C" void kernel_launch(void* const* d_in, const int* in_sizes, int n_in,
                              void* d_out, int out_size)
{
    (void)in_sizes; (void)n_in; (void)out_size;
    // 0 q, 1 k, 2 v, 3 mask, 4-19 weights, 20 bq, 21 bk, 22 bv, 23 bo
    WPtrs wp;
    for (int i = 0; i < 16; i++) wp.w[i] = (const float*)d_in[4 + i];

    build_wbig_kernel<<<dim3(32, 32, 4), 256>>>(wp);

    GemmArgs ga;
    for (int z = 0; z < 3; z++) {
        ga.A[z]    = (const float*)d_in[z];
        ga.bias[z] = (const float*)d_in[20 + z];
    }
    cudaFuncSetAttribute(qkv_gemm_kernel,
                         cudaFuncAttributeMaxDynamicSharedMemorySize, GEMM_SMEM_BYTES);
    cudaFuncSetAttribute(o_gemm_kernel,
                         cudaFuncAttributeMaxDynamicSharedMemorySize, GEMM_SMEM_BYTES);

    dim3 qkvgrid(DM / 128, MROWS / 128, 3);
    qkv_gemm_kernel<<<qkvgrid, 256, GEMM_SMEM_BYTES>>>(ga);

    cudaFuncSetAttribute(quat_attn_tc_kernel,
                         cudaFuncAttributeMaxDynamicSharedMemorySize, ATT_SMEM_BYTES);
    quat_attn_tc_kernel<<<dim3(SQ / 64, BSZ * NH), 256, ATT_SMEM_BYTES>>>(
        (const int*)d_in[3]);

    dim3 ogrid(DM / 128, MROWS / 128);
    o_gemm_kernel<<<ogrid, 256, GEMM_SMEM_BYTES>>>((const float*)d_in[23], (float*)d_out);
}

// round 11
// speedup vs baseline: 2.4623x; 1.0797x over previous
#include <cuda_runtime.h>
#include <cuda_bf16.h>
#include <cstdint>
#include <math.h>

#define SQ   1024
#define DM   1024
#define NH   16
#define DKH  64
#define BSZ  2
#define MROWS (BSZ*SQ)

typedef uint32_t u32;

// ---------------------------------------------------------------------------
// Device scratch
// ---------------------------------------------------------------------------
__device__ __nv_bfloat16 g_Wth[4][DM*DM];  // W^T hi (K-major [n][k])
__device__ __nv_bfloat16 g_Wtl[4][DM*DM];  // W^T lo
__device__ float g_P[2][MROWS*DM];         // projected Q,K
__device__ float g_Vt[BSZ*NH*DKH*SQ];      // projected V, transposed [b,h,d,S]
__device__ float g_O[MROWS*DM];            // attention output

__constant__ int   c_SRC[16] = {0,1,2,3,  1,0,3,2,  2,3,0,1,  3,2,1,0};
__constant__ float c_SGN[16] = {1.f,1.f,1.f,1.f,  -1.f,1.f,-1.f,1.f,
                                -1.f,1.f,1.f,-1.f, -1.f,-1.f,1.f,1.f};

struct WPtrs { const float* w[16]; };
struct GemmArgs { const float* A[3]; const float* bias[3]; };

#define BFPACK(r, flo, fhi) \
    asm("cvt.rn.bf16x2.f32 %0, %1, %2;" : "=r"(r) : "f"(fhi), "f"(flo))

#define HMMA(c, a0, a1, a2, a3, b0, b1) \
    asm volatile("mma.sync.aligned.m16n8k16.row.col.f32.bf16.bf16.f32 " \
        "{%0,%1,%2,%3}, {%4,%5,%6,%7}, {%8,%9}, {%0,%1,%2,%3};" \
        : "+f"((c)[0]), "+f"((c)[1]), "+f"((c)[2]), "+f"((c)[3]) \
        : "r"(a0), "r"(a1), "r"(a2), "r"(a3), "r"(b0), "r"(b1))

#define SGNM 0x80008000u

// ---------------------------------------------------------------------------
__global__ __launch_bounds__(256)
void build_wbig_kernel(WPtrs p) {
    __shared__ float s[32][33];
    int tx = threadIdx.x & 31, ty = threadIdx.x >> 5;
    int k0 = blockIdx.x * 32, n0 = blockIdx.y * 32, which = blockIdx.z;
    int rb = k0 >> 8, cb = n0 >> 8;
    float sgn = c_SGN[rb * 4 + cb];
    const float* src = p.w[which * 4 + c_SRC[rb * 4 + cb]];
#pragma unroll
    for (int i = 0; i < 4; i++) {
        int kl = ty + i * 8;
        s[kl][tx] = sgn * src[((k0 + kl) & 255) * 256 + ((n0 + tx) & 255)];
    }
    __syncthreads();
#pragma unroll
    for (int i = 0; i < 4; i++) {
        int nl = ty + i * 8;
        float v = s[tx][nl];
        __nv_bfloat16 hi = __float2bfloat16_rn(v);
        __nv_bfloat16 lo = __float2bfloat16_rn(v - __bfloat162float(hi));
        size_t o = (size_t)(n0 + nl) * DM + k0 + tx;
        g_Wth[which][o] = hi;
        g_Wtl[which][o] = lo;
    }
}

// ---------------------------------------------------------------------------
// Tensor-core GEMM, double-buffered, 2 CTAs/SM.
// ---------------------------------------------------------------------------
#define KCP 40
#define GST (128 * KCP)
#define GEMM_SMEM_BYTES (2 * 4 * GST * 2)  // 81920 B

__device__ __forceinline__
void gemm_store_stage(__nv_bfloat16* base, int tid,
                      const float4 aR[4], const uint4 whR[2], const uint4 wlR[2])
{
    __nv_bfloat16* Ah_s = base;
    __nv_bfloat16* Al_s = base + GST;
    __nv_bfloat16* Wh_s = base + 2 * GST;
    __nv_bfloat16* Wl_s = base + 3 * GST;
#pragma unroll
    for (int i = 0; i < 4; i++) {
        int idx = tid + i * 256;
        int r = idx >> 3, c4 = (idx & 7) * 4;
        float4 a = aR[i];
        u32 h01, h23, l01, l23;
        BFPACK(h01, a.x, a.y);
        BFPACK(h23, a.z, a.w);
        float rx = a.x - __uint_as_float(h01 << 16);
        float ry = a.y - __uint_as_float(h01 & 0xffff0000u);
        float rz = a.z - __uint_as_float(h23 << 16);
        float rw = a.w - __uint_as_float(h23 & 0xffff0000u);
        BFPACK(l01, rx, ry);
        BFPACK(l23, rz, rw);
        int so = r * KCP + c4;
        *(uint2*)(Ah_s + so) = make_uint2(h01, h23);
        *(uint2*)(Al_s + so) = make_uint2(l01, l23);
    }
#pragma unroll
    for (int i = 0; i < 2; i++) {
        int idx = tid + i * 256;
        int r = idx >> 2, c8 = (idx & 3) * 8;
        int so = r * KCP + c8;
        *(uint4*)(Wh_s + so) = whR[i];
        *(uint4*)(Wl_s + so) = wlR[i];
    }
}

__device__ __forceinline__
void tc_gemm_body(__nv_bfloat16* gsm, const float* __restrict__ A,
                  const __nv_bfloat16* __restrict__ Wh,
                  const __nv_bfloat16* __restrict__ Wl,
                  const float* __restrict__ bias, float* __restrict__ C, int vt)
{
    int tid = threadIdx.x;
    int wid = tid >> 5, lane = tid & 31;
    int gid = lane >> 2, tig = lane & 3;
    int wm = wid & 1, wn = wid >> 1;
    int m0 = blockIdx.y * 128, n0 = blockIdx.x * 128;

    float acc[4][4][4];
#pragma unroll
    for (int mi = 0; mi < 4; mi++)
#pragma unroll
        for (int ni = 0; ni < 4; ni++)
#pragma unroll
            for (int j = 0; j < 4; j++) acc[mi][ni][j] = 0.f;

    float4 aR[4]; uint4 whR[2], wlR[2];
    {
        const float* Ar = A + (size_t)m0 * DM;
#pragma unroll
        for (int i = 0; i < 4; i++) {
            int idx = tid + i * 256;
            int r = idx >> 3, c4 = (idx & 7) * 4;
            aR[i] = *(const float4*)(Ar + (size_t)r * DM + c4);
        }
#pragma unroll
        for (int i = 0; i < 2; i++) {
            int idx = tid + i * 256;
            int r = idx >> 2, c8 = (idx & 3) * 8;
            size_t go = (size_t)(n0 + r) * DM + c8;
            whR[i] = *(const uint4*)(Wh + go);
            wlR[i] = *(const uint4*)(Wl + go);
        }
    }
    gemm_store_stage(gsm, tid, aR, whR, wlR);
    __syncthreads();

    for (int kt = 0; kt < 32; kt++) {
        if (kt < 31) {
            int k0n = (kt + 1) * 32;
            const float* Ar = A + (size_t)m0 * DM + k0n;
#pragma unroll
            for (int i = 0; i < 4; i++) {
                int idx = tid + i * 256;
                int r = idx >> 3, c4 = (idx & 7) * 4;
                aR[i] = *(const float4*)(Ar + (size_t)r * DM + c4);
            }
#pragma unroll
            for (int i = 0; i < 2; i++) {
                int idx = tid + i * 256;
                int r = idx >> 2, c8 = (idx & 3) * 8;
                size_t go = (size_t)(n0 + r) * DM + k0n + c8;
                whR[i] = *(const uint4*)(Wh + go);
                wlR[i] = *(const uint4*)(Wl + go);
            }
        }

        __nv_bfloat16* st = gsm + (size_t)(kt & 1) * 4 * GST;
        __nv_bfloat16* Ah_s = st;
        __nv_bfloat16* Al_s = st + GST;
        __nv_bfloat16* Wh_s = st + 2 * GST;
        __nv_bfloat16* Wl_s = st + 3 * GST;

#pragma unroll
        for (int ks = 0; ks < 2; ks++) {
            int kb = ks * 16 + tig * 2;
            u32 bh[4][2], bl[4][2];
#pragma unroll
            for (int ni = 0; ni < 4; ni++) {
                int n = wn * 32 + ni * 8 + gid;
                int off = n * KCP + kb;
                bh[ni][0] = *(const u32*)(Wh_s + off);
                bh[ni][1] = *(const u32*)(Wh_s + off + 8);
                bl[ni][0] = *(const u32*)(Wl_s + off);
                bl[ni][1] = *(const u32*)(Wl_s + off + 8);
            }
#pragma unroll
            for (int mi = 0; mi < 4; mi++) {
                int r = wm * 64 + mi * 16 + gid;
                int off = r * KCP + kb;
                u32 ah0 = *(const u32*)(Ah_s + off);
                u32 ah1 = *(const u32*)(Ah_s + off + 8 * KCP);
                u32 ah2 = *(const u32*)(Ah_s + off + 8);
                u32 ah3 = *(const u32*)(Ah_s + off + 8 * KCP + 8);
                u32 al0 = *(const u32*)(Al_s + off);
                u32 al1 = *(const u32*)(Al_s + off + 8 * KCP);
                u32 al2 = *(const u32*)(Al_s + off + 8);
                u32 al3 = *(const u32*)(Al_s + off + 8 * KCP + 8);
#pragma unroll
                for (int ni = 0; ni < 4; ni++) {
                    HMMA(acc[mi][ni], ah0, ah1, ah2, ah3, bh[ni][0], bh[ni][1]);
                    HMMA(acc[mi][ni], ah0, ah1, ah2, ah3, bl[ni][0], bl[ni][1]);
                    HMMA(acc[mi][ni], al0, al1, al2, al3, bh[ni][0], bh[ni][1]);
                }
            }
        }
        if (kt < 31)
            gemm_store_stage(gsm + (size_t)((kt + 1) & 1) * 4 * GST, tid, aR, whR, wlR);
        __syncthreads();
    }

#pragma unroll
    for (int mi = 0; mi < 4; mi++) {
        int r = m0 + wm * 64 + mi * 16 + gid;
#pragma unroll
        for (int ni = 0; ni < 4; ni++) {
            int c = n0 + wn * 32 + ni * 8 + tig * 2;
            float b0 = bias[c], b1 = bias[c + 1];
            if (!vt) {
                *(float2*)(C + (size_t)r * DM + c) =
                    make_float2(acc[mi][ni][0] + b0, acc[mi][ni][1] + b1);
                *(float2*)(C + (size_t)(r + 8) * DM + c) =
                    make_float2(acc[mi][ni][2] + b0, acc[mi][ni][3] + b1);
            } else {
                int b = r >> 10, s = r & 1023;
                int h = c >> 6, d = c & 63;
                float* base = g_Vt + ((size_t)(b * NH + h) * DKH) * SQ;
                base[(size_t)d * SQ + s]           = acc[mi][ni][0] + b0;
                base[(size_t)(d + 1) * SQ + s]     = acc[mi][ni][1] + b1;
                base[(size_t)d * SQ + s + 8]       = acc[mi][ni][2] + b0;
                base[(size_t)(d + 1) * SQ + s + 8] = acc[mi][ni][3] + b1;
            }
        }
    }
}

__global__ __launch_bounds__(256, 2)
void qkv_gemm_kernel(GemmArgs args) {
    extern __shared__ __nv_bfloat16 gsm[];
    int z = blockIdx.z;
    tc_gemm_body(gsm, args.A[z], g_Wth[z], g_Wtl[z], args.bias[z],
                 z < 2 ? g_P[z] : nullptr, z == 2);
}
__global__ __launch_bounds__(256, 2)
void o_gemm_kernel(const float* __restrict__ bias, float* __restrict__ Cout) {
    extern __shared__ __nv_bfloat16 gsm[];
    tc_gemm_body(gsm, g_O, g_Wth[3], g_Wtl[3], bias, Cout, 0);
}

// ---------------------------------------------------------------------------
// Tensor-core quaternion flash attention, with K/V register prefetch.
// ---------------------------------------------------------------------------
#define STR 72
#define TILE_B (64*STR)

#define S_QH  0
#define S_QL  (S_QH + TILE_B)
#define S_KH  (S_QL + TILE_B)
#define S_KL  (S_KH + TILE_B)
#define S_VH  (S_KL + TILE_B)
#define S_VL  (S_VH + TILE_B)
#define S_PH  (S_VL + TILE_B)           // [4][64][STR]
#define S_PL  (S_PH + 4*TILE_B)
#define S_END (S_PL + 4*TILE_B)
#define ATT_SMEM_BYTES (S_END*2 + 4*64*2*8 + 256)

// convert float4 to bf16 hi/lo pairs and store at smem offset
__device__ __forceinline__
void kv_store_one(__nv_bfloat16* sm, int hioff, int looff, int so, float4 a)
{
    u32 h01, h23, l01, l23;
    BFPACK(h01, a.x, a.y);
    BFPACK(h23, a.z, a.w);
    float rx = a.x - __uint_as_float(h01 << 16);
    float ry = a.y - __uint_as_float(h01 & 0xffff0000u);
    float rz = a.z - __uint_as_float(h23 << 16);
    float rw = a.w - __uint_as_float(h23 & 0xffff0000u);
    BFPACK(l01, rx, ry);
    BFPACK(l23, rz, rw);
    *(uint2*)(sm + hioff + so) = make_uint2(h01, h23);
    *(uint2*)(sm + looff + so) = make_uint2(l01, l23);
}

__global__ __launch_bounds__(256, 1)
void quat_attn_tc_kernel(const int* __restrict__ mask)
{
    extern __shared__ __nv_bfloat16 sm[];
    float2* stats2 = (float2*)(sm + S_END);     // [4][64][2] (max, expsum)
    int*    msk    = (int*)(stats2 + 4 * 64 * 2);

    const int tsrc[4][4] = {{0,1,2,3},{1,0,3,2},{2,3,0,1},{3,2,1,0}};
    const int tsgn[4][4] = {{1,1,1,1},{-1,1,-1,1},{-1,1,1,-1},{-1,-1,1,1}};

    int tid = threadIdx.x;
    int wid = tid >> 5, lane = tid & 31;
    int gid = lane >> 2, tig = lane & 3;
    int mtile = wid >> 1, wh = wid & 1;
    int m16 = mtile * 16;
    int bh = blockIdx.y;
    int b = bh >> 4, h = bh & 15;
    int q0 = blockIdx.x * 64;

    const float* Qg = g_P[0] + (size_t)(b * SQ) * DM + h * DKH;
    const float* Kg = g_P[1] + (size_t)(b * SQ) * DM + h * DKH;
    const float* Vg = g_Vt + (size_t)bh * DKH * SQ;
    const int*   mrow = mask + b * SQ;

    int ldr = tid >> 4, ldc = (tid & 15) * 4;   // per-thread load coords

    // ---- load Q tile (scaled by 1/8) ----
#pragma unroll
    for (int i = 0; i < 4; i++) {
        int r = ldr + i * 16;
        float4 a = *(const float4*)(Qg + (size_t)(q0 + r) * DM + ldc);
        a.x *= 0.125f; a.y *= 0.125f; a.z *= 0.125f; a.w *= 0.125f;
        kv_store_one(sm, S_QH, S_QL, r * STR + ldc, a);
    }
    __syncthreads();

    // ---- persistent Q fragments ----
    u32 qfh[4][4], qfl[4][4];
#pragma unroll
    for (int u = 0; u < 4; u++) {
        int off = (m16 + gid) * STR + u * 16 + tig * 2;
        qfh[u][0] = *(const u32*)(sm + S_QH + off);
        qfh[u][1] = *(const u32*)(sm + S_QH + off + 8 * STR);
        qfh[u][2] = *(const u32*)(sm + S_QH + off + 8);
        qfh[u][3] = *(const u32*)(sm + S_QH + off + 8 * STR + 8);
        qfl[u][0] = *(const u32*)(sm + S_QL + off);
        qfl[u][1] = *(const u32*)(sm + S_QL + off + 8 * STR);
        qfl[u][2] = *(const u32*)(sm + S_QL + off + 8);
        qfl[u][3] = *(const u32*)(sm + S_QL + off + 8 * STR + 8);
    }

    float mrun[4][2], lrun[4][2];
    float U[4][4][4];
#pragma unroll
    for (int c = 0; c < 4; c++) {
#pragma unroll
        for (int j = 0; j < 2; j++) { mrun[c][j] = -1e30f; lrun[c][j] = 0.f; }
#pragma unroll
        for (int nt = 0; nt < 4; nt++)
#pragma unroll
            for (int j = 0; j < 4; j++) U[c][nt][j] = 0.f;
    }

    float4 kR[4], vR[4];
    // preload tile 0 into regs, store to smem
#pragma unroll
    for (int i = 0; i < 4; i++) {
        int r = ldr + i * 16;
        kR[i] = *(const float4*)(Kg + (size_t)r * DM + ldc);
        vR[i] = *(const float4*)(Vg + (size_t)r * SQ + ldc);
    }
#pragma unroll
    for (int i = 0; i < 4; i++) {
        int r = ldr + i * 16;
        kv_store_one(sm, S_KH, S_KL, r * STR + ldc, kR[i]);
        kv_store_one(sm, S_VH, S_VL, r * STR + ldc, vR[i]);
    }
    if (tid < 64) msk[tid] = mrow[tid];
    __syncthreads();

    for (int t = 0; t < 16; t++) {
        int n0 = t * 64;
        // prefetch next tile K/V into registers (overlaps all compute below)
        if (t < 15) {
            int n1 = n0 + 64;
#pragma unroll
            for (int i = 0; i < 4; i++) {
                int r = ldr + i * 16;
                kR[i] = *(const float4*)(Kg + (size_t)(n1 + r) * DM + ldc);
                vR[i] = *(const float4*)(Vg + (size_t)r * SQ + n1 + ldc);
            }
        }

        // ---- score MMAs ----
        float sc[4][4][4];
#pragma unroll
        for (int c = 0; c < 4; c++)
#pragma unroll
            for (int nt = 0; nt < 4; nt++)
#pragma unroll
                for (int j = 0; j < 4; j++) sc[c][nt][j] = 0.f;

#pragma unroll
        for (int nt = 0; nt < 4; nt++) {
            int kb0 = wh * 32 + nt * 8;
            u32 kf[4][2][2];
#pragma unroll
            for (int comp = 0; comp < 4; comp++) {
                int off = (kb0 + gid) * STR + comp * 16 + tig * 2;
                kf[comp][0][0] = *(const u32*)(sm + S_KH + off);
                kf[comp][0][1] = *(const u32*)(sm + S_KH + off + 8);
                kf[comp][1][0] = *(const u32*)(sm + S_KL + off);
                kf[comp][1][1] = *(const u32*)(sm + S_KL + off + 8);
            }
#pragma unroll
            for (int c = 0; c < 4; c++)
#pragma unroll
                for (int u = 0; u < 4; u++) {
                    int src = tsrc[u][c];
                    u32 bh0 = kf[src][0][0], bh1 = kf[src][0][1];
                    u32 bl0 = kf[src][1][0], bl1 = kf[src][1][1];
                    if (tsgn[u][c] < 0) {
                        bh0 ^= SGNM; bh1 ^= SGNM; bl0 ^= SGNM; bl1 ^= SGNM;
                    }
                    HMMA(sc[c][nt], qfh[u][0], qfh[u][1], qfh[u][2], qfh[u][3], bh0, bh1);
                    HMMA(sc[c][nt], qfh[u][0], qfh[u][1], qfh[u][2], qfh[u][3], bl0, bl1);
                    HMMA(sc[c][nt], qfl[u][0], qfl[u][1], qfl[u][2], qfl[u][3], bh0, bh1);
                }
        }

        // ---- mask ----
#pragma unroll
        for (int nt = 0; nt < 4; nt++) {
            int kb0 = wh * 32 + nt * 8 + tig * 2;
            int m0v = msk[kb0], m1v = msk[kb0 + 1];
#pragma unroll
            for (int c = 0; c < 4; c++) {
                if (!m0v) { sc[c][nt][0] = -1e9f; sc[c][nt][2] = -1e9f; }
                if (!m1v) { sc[c][nt][1] = -1e9f; sc[c][nt][3] = -1e9f; }
            }
        }

        // ---- per-warp tile softmax, single exchange ----
        float tmx[4][2], tsum[4][2];
#pragma unroll
        for (int c = 0; c < 4; c++) {
            float t0 = -1e30f, t1 = -1e30f;
#pragma unroll
            for (int nt = 0; nt < 4; nt++) {
                t0 = fmaxf(t0, fmaxf(sc[c][nt][0], sc[c][nt][1]));
                t1 = fmaxf(t1, fmaxf(sc[c][nt][2], sc[c][nt][3]));
            }
            t0 = fmaxf(t0, __shfl_xor_sync(0xffffffffu, t0, 1));
            t0 = fmaxf(t0, __shfl_xor_sync(0xffffffffu, t0, 2));
            t1 = fmaxf(t1, __shfl_xor_sync(0xffffffffu, t1, 1));
            t1 = fmaxf(t1, __shfl_xor_sync(0xffffffffu, t1, 2));
            float s0 = 0.f, s1 = 0.f;
#pragma unroll
            for (int nt = 0; nt < 4; nt++) {
                sc[c][nt][0] = __expf(sc[c][nt][0] - t0);
                sc[c][nt][1] = __expf(sc[c][nt][1] - t0);
                sc[c][nt][2] = __expf(sc[c][nt][2] - t1);
                sc[c][nt][3] = __expf(sc[c][nt][3] - t1);
                s0 += sc[c][nt][0] + sc[c][nt][1];
                s1 += sc[c][nt][2] + sc[c][nt][3];
            }
            s0 += __shfl_xor_sync(0xffffffffu, s0, 1);
            s0 += __shfl_xor_sync(0xffffffffu, s0, 2);
            s1 += __shfl_xor_sync(0xffffffffu, s1, 1);
            s1 += __shfl_xor_sync(0xffffffffu, s1, 2);
            tmx[c][0] = t0; tmx[c][1] = t1;
            tsum[c][0] = s0; tsum[c][1] = s1;
            if (tig == 0) {
                stats2[(c * 64 + m16 + gid) * 2 + wh] = make_float2(t0, s0);
                stats2[(c * 64 + m16 + gid + 8) * 2 + wh] = make_float2(t1, s1);
            }
        }
        __syncthreads();

        // ---- merge with partner half, rescale U, pack scaled P ----
#pragma unroll
        for (int c = 0; c < 4; c++) {
            float2 o0 = stats2[(c * 64 + m16 + gid) * 2 + (wh ^ 1)];
            float2 o1 = stats2[(c * 64 + m16 + gid + 8) * 2 + (wh ^ 1)];
            float mn0 = fmaxf(mrun[c][0], fmaxf(tmx[c][0], o0.x));
            float mn1 = fmaxf(mrun[c][1], fmaxf(tmx[c][1], o1.x));
            float corr0 = __expf(mrun[c][0] - mn0);
            float corr1 = __expf(mrun[c][1] - mn1);
            float f0 = __expf(tmx[c][0] - mn0);
            float f1 = __expf(tmx[c][1] - mn1);
            float g0 = __expf(o0.x - mn0);
            float g1 = __expf(o1.x - mn1);
            lrun[c][0] = lrun[c][0] * corr0 + tsum[c][0] * f0 + o0.y * g0;
            lrun[c][1] = lrun[c][1] * corr1 + tsum[c][1] * f1 + o1.y * g1;
            mrun[c][0] = mn0; mrun[c][1] = mn1;
#pragma unroll
            for (int nt = 0; nt < 4; nt++) {
                U[c][nt][0] *= corr0;
                U[c][nt][1] *= corr0;
                U[c][nt][2] *= corr1;
                U[c][nt][3] *= corr1;
            }
#pragma unroll
            for (int nt = 0; nt < 4; nt++) {
                int key = wh * 32 + nt * 8 + tig * 2;
                float p0 = sc[c][nt][0] * f0, p1 = sc[c][nt][1] * f0;
                u32 h01, l01;
                BFPACK(h01, p0, p1);
                float rx = p0 - __uint_as_float(h01 << 16);
                float ry = p1 - __uint_as_float(h01 & 0xffff0000u);
                BFPACK(l01, rx, ry);
                int ro = (c * 64 + m16 + gid) * STR + key;
                *(u32*)(sm + S_PH + ro) = h01;
                *(u32*)(sm + S_PL + ro) = l01;
                float p2 = sc[c][nt][2] * f1, p3 = sc[c][nt][3] * f1;
                BFPACK(h01, p2, p3);
                rx = p2 - __uint_as_float(h01 << 16);
                ry = p3 - __uint_as_float(h01 & 0xffff0000u);
                BFPACK(l01, rx, ry);
                ro = (c * 64 + m16 + gid + 8) * STR + key;
                *(u32*)(sm + S_PH + ro) = h01;
                *(u32*)(sm + S_PL + ro) = l01;
            }
        }
        __syncthreads();

        // ---- PV MMAs ----
#pragma unroll
        for (int c = 0; c < 4; c++) {
#pragma unroll
            for (int u = 0; u < 4; u++) {
                int ao = (c * 64 + m16 + gid) * STR + u * 16 + tig * 2;
                u32 pa0 = *(const u32*)(sm + S_PH + ao);
                u32 pa1 = *(const u32*)(sm + S_PH + ao + 8 * STR);
                u32 pa2 = *(const u32*)(sm + S_PH + ao + 8);
                u32 pa3 = *(const u32*)(sm + S_PH + ao + 8 * STR + 8);
                u32 la0 = *(const u32*)(sm + S_PL + ao);
                u32 la1 = *(const u32*)(sm + S_PL + ao + 8 * STR);
                u32 la2 = *(const u32*)(sm + S_PL + ao + 8);
                u32 la3 = *(const u32*)(sm + S_PL + ao + 8 * STR + 8);
#pragma unroll
                for (int nt = 0; nt < 4; nt++) {
                    int oc = wh * 2 + (nt >> 1);
                    int src = tsrc[c][oc];
                    u32 smask = (tsgn[c][oc] < 0) ? SGNM : 0u;
                    int bo = (src * 16 + (nt & 1) * 8 + gid) * STR + u * 16 + tig * 2;
                    u32 vh0 = *(const u32*)(sm + S_VH + bo) ^ smask;
                    u32 vh1 = *(const u32*)(sm + S_VH + bo + 8) ^ smask;
                    u32 vl0 = *(const u32*)(sm + S_VL + bo) ^ smask;
                    u32 vl1 = *(const u32*)(sm + S_VL + bo + 8) ^ smask;
                    HMMA(U[c][nt], pa0, pa1, pa2, pa3, vh0, vh1);
                    HMMA(U[c][nt], pa0, pa1, pa2, pa3, vl0, vl1);
                    HMMA(U[c][nt], la0, la1, la2, la3, vh0, vh1);
                }
            }
        }
        __syncthreads();   // PV reads done before K/V overwrite

        if (t < 15) {
#pragma unroll
            for (int i = 0; i < 4; i++) {
                int r = ldr + i * 16;
                kv_store_one(sm, S_KH, S_KL, r * STR + ldc, kR[i]);
                kv_store_one(sm, S_VH, S_VL, r * STR + ldc, vR[i]);
            }
            if (tid < 64) msk[tid] = mrow[n0 + 64 + tid];
            __syncthreads();
        }
    }

    // ---- register epilogue ----
    float inv[4][2];
#pragma unroll
    for (int c = 0; c < 4; c++) {
        inv[c][0] = 1.f / lrun[c][0];
        inv[c][1] = 1.f / lrun[c][1];
    }
    float* Og = g_O + (size_t)(b * SQ) * DM + h * DKH;
    int r0 = q0 + m16 + gid;
#pragma unroll
    for (int nt = 0; nt < 4; nt++) {
        int col = wh * 32 + nt * 8 + tig * 2;
        float o0 = 0.f, o1 = 0.f, o2 = 0.f, o3 = 0.f;
#pragma unroll
        for (int c = 0; c < 4; c++) {
            o0 += U[c][nt][0] * inv[c][0];
            o1 += U[c][nt][1] * inv[c][0];
            o2 += U[c][nt][2] * inv[c][1];
            o3 += U[c][nt][3] * inv[c][1];
        }
        *(float2*)(Og + (size_t)r0 * DM + col) = make_float2(o0, o1);
        *(float2*)(Og + (size_t)(r0 + 8) * DM + col) = make_float2(o2, o3);
    }
}

// ---------------------------------------------------------------------------
extern "C" void kernel_launch(void* const* d_in, const int* in_sizes, int n_in,
                              void* d_out, int out_size)
{
    (void)in_sizes; (void)n_in; (void)out_size;
    // 0 q, 1 k, 2 v, 3 mask, 4-19 weights, 20 bq, 21 bk, 22 bv, 23 bo
    WPtrs wp;
    for (int i = 0; i < 16; i++) wp.w[i] = (const float*)d_in[4 + i];

    build_wbig_kernel<<<dim3(32, 32, 4), 256>>>(wp);

    GemmArgs ga;
    for (int z = 0; z < 3; z++) {
        ga.A[z]    = (const float*)d_in[z];
        ga.bias[z] = (const float*)d_in[20 + z];
    }
    cudaFuncSetAttribute(qkv_gemm_kernel,
                         cudaFuncAttributeMaxDynamicSharedMemorySize, GEMM_SMEM_BYTES);
    cudaFuncSetAttribute(o_gemm_kernel,
                         cudaFuncAttributeMaxDynamicSharedMemorySize, GEMM_SMEM_BYTES);

    dim3 qkvgrid(DM / 128, MROWS / 128, 3);
    qkv_gemm_kernel<<<qkvgrid, 256, GEMM_SMEM_BYTES>>>(ga);

    cudaFuncSetAttribute(quat_attn_tc_kernel,
                         cudaFuncAttributeMaxDynamicSharedMemorySize, ATT_SMEM_BYTES);
    quat_attn_tc_kernel<<<dim3(SQ / 64, BSZ * NH), 256, ATT_SMEM_BYTES>>>(
        (const int*)d_in[3]);

    dim3 ogrid(DM / 128, MROWS / 128);
    o_gemm_kernel<<<ogrid, 256, GEMM_SMEM_BYTES>>>((const float*)d_in[23], (float*)d_out);
}